// round 14
// baseline (speedup 1.0000x reference)
#include <cuda_runtime.h>
#include <cstdint>
#include <mma.h>
using namespace nvcuda;

#define NTOK 10001
#define CDIM 512
#define NP   10240
#define PADN 239
#define NH   8
#define DH   64
#define NL   256
#define LW   40
#define KQKV (3*CDIM)
#define MPAD 10112

constexpr long SZ_H    = (long)NTOK*CDIM;
constexpr long SZ_LNX  = (long)NP*CDIM;
constexpr long SZ_QKV  = (long)NP*KQKV;
constexpr long SZ_LAND = (long)NH*NL*DH;
constexpr long SZ_A1   = (long)NH*NP*NL;
constexpr long SZ_A2   = (long)NH*NL*NL;

constexpr long OFF_HA   = 0;
constexpr long OFF_HB   = OFF_HA  + SZ_H;
constexpr long OFF_LNX  = OFF_HB  + SZ_H;
constexpr long OFF_QKV  = OFF_LNX + SZ_LNX;
constexpr long OFF_QL   = OFF_QKV + SZ_QKV;
constexpr long OFF_KL   = OFF_QL  + SZ_LAND;
constexpr long OFF_A1   = OFF_KL  + SZ_LAND;
constexpr long OFF_A3   = OFF_A1  + SZ_A1;
constexpr long OFF_A2   = OFF_A3  + SZ_A1;
constexpr long OFF_ZA   = OFF_A2  + SZ_A2;
constexpr long OFF_ZB   = OFF_ZA  + SZ_A2;
constexpr long OFF_XZ   = OFF_ZB  + SZ_A2;
constexpr long OFF_TB   = OFF_XZ  + SZ_A2;
constexpr long OFF_UB   = OFF_TB  + SZ_A2;
constexpr long OFF_CS   = OFF_UB  + SZ_A2;
constexpr long OFF_RS   = OFF_CS  + 2048;
constexpr long OFF_SC   = OFF_RS  + 2048;
constexpr long OFF_A3VP = OFF_SC  + 8;
constexpr long SZ_A3VP  = (long)NH*32*NL*DH;
constexpr long OFF_A3V  = OFF_A3VP + SZ_A3VP;
constexpr long OFF_W2   = OFF_A3V + SZ_LAND;
constexpr long OFF_ATT  = OFF_W2  + SZ_LAND;
constexpr long OFF_TMP  = OFF_ATT + SZ_LNX;
constexpr long OFF_WC   = OFF_TMP + (long)MPAD*CDIM;
constexpr long OFF_CNT  = OFF_WC + 512*49;
constexpr long OFF_W1R  = OFF_CNT + 256;
constexpr long OFF_O1R  = OFF_W1R + (long)CDIM*KQKV;
constexpr long OFF_W2R  = OFF_O1R + (long)CDIM*CDIM;
constexpr long OFF_O2R  = OFF_W2R + (long)CDIM*KQKV;
constexpr long OFF_M3   = OFF_O2R + (long)CDIM*CDIM;
constexpr long OFF_I3   = OFF_M3 + 2048;
constexpr long SCRATCH_SZ = OFF_I3 + 2048 + 64;

static __device__ float g_scratch[SCRATCH_SZ];

__device__ __forceinline__ float tf32r(float x){
  unsigned int u;
  asm("cvt.rna.tf32.f32 %0, %1;\n" : "=r"(u) : "f"(x));
  return __uint_as_float(u);
}

__device__ __forceinline__ float warpMax(float v){
  #pragma unroll
  for (int o=16;o;o>>=1) v = fmaxf(v, __shfl_xor_sync(0xffffffffu, v, o));
  return v;
}
__device__ __forceinline__ float warpSum(float v){
  #pragma unroll
  for (int o=16;o;o>>=1) v += __shfl_xor_sync(0xffffffffu, v, o);
  return v;
}

__device__ __forceinline__ void cp16(float* dst, const float* src, bool ok){
  unsigned int d = (unsigned int)__cvta_generic_to_shared(dst);
  int b = ok ? 16 : 0;
  asm volatile("cp.async.cg.shared.global [%0], [%1], 16, %2;\n" :: "r"(d), "l"(src), "r"(b));
}

__global__ void round_copy_k(const float* __restrict__ in, float* __restrict__ out, long n){
  long i = (long)blockIdx.x*256 + threadIdx.x;
  if (i < n) out[i] = tf32r(in[i]);
}

__global__ void init_h_k(const float* __restrict__ feat, const float* __restrict__ cls,
                         float* __restrict__ h){
  long i = (long)blockIdx.x*256 + threadIdx.x;
  if (i >= SZ_H) return;
  h[i] = (i < CDIM) ? cls[i] : feat[i - CDIM];
}

__global__ void zero_k(float* __restrict__ p, long n){
  long i = (long)blockIdx.x*256 + threadIdx.x;
  if (i < n) p[i] = 0.f;
}

template<bool RND>
__global__ void ln_k(const float* __restrict__ x, float* __restrict__ y,
                     const float* __restrict__ g, const float* __restrict__ b){
  const int t = blockIdx.x;
  const float* xr = x + (long)t*CDIM;
  float* yr = y + (long)t*CDIM;
  int tid = threadIdx.x;
  float s = 0.f, s2 = 0.f;
  #pragma unroll
  for (int c = tid; c < CDIM; c += 128){ float v = xr[c]; s += v; s2 += v*v; }
  #pragma unroll
  for (int o=16;o;o>>=1){ s += __shfl_xor_sync(0xffffffffu,s,o); s2 += __shfl_xor_sync(0xffffffffu,s2,o); }
  __shared__ float sm[4], sm2[4];
  if ((tid&31)==0){ sm[tid>>5]=s; sm2[tid>>5]=s2; }
  __syncthreads();
  s  = sm[0]+sm[1]+sm[2]+sm[3];
  s2 = sm2[0]+sm2[1]+sm2[2]+sm2[3];
  float mu  = s * (1.f/CDIM);
  float var = s2 * (1.f/CDIM) - mu*mu;
  float inv = rsqrtf(var + 1e-5f);
  #pragma unroll
  for (int c = tid; c < CDIM; c += 128){
    float v = (xr[c]-mu)*inv*g[c] + b[c];
    yr[c] = RND ? tf32r(v) : v;
  }
}

// ---------- 3-stage pipelined tf32 GEMM ----------
template<int BN, bool NT, bool RND>
__global__ void __launch_bounds__(256,2) gemm_tc(
                        const float* __restrict__ A, int lda, long sA,
                        const float* __restrict__ B, int ldb, long sB,
                        float* __restrict__ C, int ldc, long sC,
                        int M, int N, int K, float alpha)
{
  constexpr int BM=128, BK=32, BKP=36, BNP=BN+4;
  constexpr int WN = BN/2, NF = WN/16;
  constexpr int ASZ = BM*BKP;
  constexpr int BSZ = NT ? BN*BKP : BK*BNP;
  extern __shared__ float dyn[];
  float* Asm = dyn;              // [3][ASZ]
  float* Bsm = dyn + 3*ASZ;      // [3][BSZ]

  const int tid = threadIdx.x;
  const int wid = tid >> 5;
  const int warp_m = wid & 3, warp_n = wid >> 2;
  const int bm = blockIdx.y*BM, bn = blockIdx.x*BN;
  A += (long)blockIdx.z * sA;
  B += (long)blockIdx.z * sB;
  C += (long)blockIdx.z * sC;

  wmma::fragment<wmma::accumulator,16,16,8,float> acc[2][NF];
  #pragma unroll
  for (int im=0;im<2;im++)
    #pragma unroll
    for (int jn=0;jn<NF;jn++) wmma::fill_fragment(acc[im][jn], 0.f);

  auto loadA = [&](int s, int k0){
    float* As = Asm + s*ASZ;
    #pragma unroll
    for (int i=0;i<4;i++){
      int lin = tid + i*256;
      int r = lin >> 3, k4 = (lin & 7)*4;
      int gr = bm + r;
      bool ok = gr < M;
      const float* src = A + (long)(ok ? gr : bm)*lda + k0 + k4;
      cp16(As + r*BKP + k4, src, ok);
    }
  };
  auto loadB = [&](int s, int k0){
    float* Bs = Bsm + s*BSZ;
    if (!NT){
      constexpr int NB4 = (BK*BN/4)/256;
      #pragma unroll
      for (int i=0;i<NB4;i++){
        int lin = tid + i*256;
        int kk = lin / (BN/4), c4 = (lin % (BN/4))*4;
        cp16(Bs + kk*BNP + c4, B + (long)(k0+kk)*ldb + bn + c4, true);
      }
    } else {
      constexpr int NB4 = (BN*BK/4)/256;
      #pragma unroll
      for (int i=0;i<NB4;i++){
        int lin = tid + i*256;
        int c = lin >> 3, k4 = (lin & 7)*4;
        cp16(Bs + c*BKP + k4, B + (long)(bn+c)*ldb + k0 + k4, true);
      }
    }
  };

  const int nt = K/BK;
  loadA(0, 0); loadB(0, 0);
  asm volatile("cp.async.commit_group;\n");
  if (nt > 1){
    loadA(1, BK); loadB(1, BK);
    asm volatile("cp.async.commit_group;\n");
  }
  for (int t=0; t<nt; t++){
    if (t+2 < nt){
      loadA((t+2)%3, (t+2)*BK);
      loadB((t+2)%3, (t+2)*BK);
      asm volatile("cp.async.commit_group;\n");
    }
    int rem = nt-1-t;
    if (rem >= 2)      asm volatile("cp.async.wait_group 2;\n");
    else if (rem == 1) asm volatile("cp.async.wait_group 1;\n");
    else               asm volatile("cp.async.wait_group 0;\n");
    __syncthreads();
    int cs = t % 3;
    float* As = Asm + cs*ASZ;
    float* Bs = Bsm + cs*BSZ;
    #pragma unroll
    for (int kk=0; kk<BK; kk+=8){
      wmma::fragment<wmma::matrix_a,16,16,8,wmma::precision::tf32,wmma::row_major> af[2];
      #pragma unroll
      for (int im=0;im<2;im++)
        wmma::load_matrix_sync(af[im], As + (warp_m*32 + im*16)*BKP + kk, BKP);
      if (!NT){
        wmma::fragment<wmma::matrix_b,16,16,8,wmma::precision::tf32,wmma::row_major> bf[NF];
        #pragma unroll
        for (int jn=0;jn<NF;jn++)
          wmma::load_matrix_sync(bf[jn], Bs + kk*BNP + warp_n*WN + jn*16, BNP);
        #pragma unroll
        for (int im=0;im<2;im++)
          #pragma unroll
          for (int jn=0;jn<NF;jn++)
            wmma::mma_sync(acc[im][jn], af[im], bf[jn], acc[im][jn]);
      } else {
        wmma::fragment<wmma::matrix_b,16,16,8,wmma::precision::tf32,wmma::col_major> bf[NF];
        #pragma unroll
        for (int jn=0;jn<NF;jn++)
          wmma::load_matrix_sync(bf[jn], Bs + (warp_n*WN + jn*16)*BKP + kk, BKP);
        #pragma unroll
        for (int im=0;im<2;im++)
          #pragma unroll
          for (int jn=0;jn<NF;jn++)
            wmma::mma_sync(acc[im][jn], af[im], bf[jn], acc[im][jn]);
      }
    }
    __syncthreads();
  }
  #pragma unroll
  for (int im=0;im<2;im++)
    #pragma unroll
    for (int jn=0;jn<NF;jn++){
      #pragma unroll
      for (int e=0;e<acc[im][jn].num_elements;e++){
        float v = alpha * acc[im][jn].x[e];
        acc[im][jn].x[e] = RND ? tf32r(v) : v;
      }
      wmma::store_matrix_sync(C + (long)(bm + warp_m*32 + im*16)*ldc + bn + warp_n*WN + jn*16,
                              acc[im][jn], ldc, wmma::mem_row_major);
    }
}

constexpr int DSM_NN128 = (3*(128*36) + 3*(32*132))*4;
constexpr int DSM_NT128 = (3*(128*36) + 3*(128*36))*4;
constexpr int DSM_NN64  = (3*(128*36) + 3*(32*68))*4;

__global__ void landmarks_k(const float* __restrict__ qkv,
                            float* __restrict__ ql, float* __restrict__ kl){
  int j = blockIdx.x, h = blockIdx.y, d = threadIdx.x;
  const float* base = qkv + (long)(j*LW)*KQKV + h*DH + d;
  float sq = 0.f, sk = 0.f;
  #pragma unroll 8
  for (int t=0;t<LW;t++){ sq += base[(long)t*KQKV]; sk += base[(long)t*KQKV + CDIM]; }
  long o = ((long)h*NL + j)*DH + d;
  ql[o] = tf32r(sq * (1.f/LW));
  kl[o] = tf32r(sk * (1.f/LW));
}

__global__ void softmax256(float* __restrict__ x){
  float* p = x + (long)blockIdx.x * NL;
  int tid = threadIdx.x;
  float v = p[tid];
  __shared__ float sm[8];
  float m = warpMax(v);
  if ((tid&31)==0) sm[tid>>5]=m;
  __syncthreads();
  if (tid < 32){ float t = (tid<8)? sm[tid] : -3.4e38f; t = warpMax(t); if (tid==0) sm[0]=t; }
  __syncthreads();
  m = sm[0];
  __syncthreads();
  float e = __expf(v - m);
  float s = warpSum(e);
  if ((tid&31)==0) sm[tid>>5]=s;
  __syncthreads();
  if (tid < 32){ float t = (tid<8)? sm[tid] : 0.f; t = warpSum(t); if (tid==0) sm[0]=t; }
  __syncthreads();
  p[tid] = tf32r(e / sm[0]);
}

__global__ void rowstat3_k(const float* __restrict__ a3, float* __restrict__ m3,
                           float* __restrict__ i3){
  int r = blockIdx.x, h = blockIdx.y, tid = threadIdx.x;
  const float* p = a3 + ((long)h*NL + r)*NP;
  float va[NP/256];
  float m = -3.4e38f;
  #pragma unroll
  for (int i=0;i<NP/256;i++){ va[i] = p[tid + i*256]; m = fmaxf(m, va[i]); }
  __shared__ float sm[8];
  m = warpMax(m);
  if ((tid&31)==0) sm[tid>>5]=m;
  __syncthreads();
  if (tid < 32){ float t = (tid<8)? sm[tid] : -3.4e38f; t = warpMax(t); if (tid==0) sm[0]=t; }
  __syncthreads();
  m = sm[0];
  __syncthreads();
  float s = 0.f;
  #pragma unroll
  for (int i=0;i<NP/256;i++) s += __expf(va[i]-m);
  s = warpSum(s);
  if ((tid&31)==0) sm[tid>>5]=s;
  __syncthreads();
  if (tid < 32){ float t = (tid<8)? sm[tid] : 0.f; t = warpSum(t); if (tid==0) sm[0]=t; }
  __syncthreads();
  if (tid==0){ m3[h*NL+r]=m; i3[h*NL+r]=1.f/sm[0]; }
}

__global__ void colsum_k(const float* __restrict__ a2, float* __restrict__ cs){
  int row = blockIdx.x*256 + threadIdx.x;
  const float* p = a2 + (long)row*NL;
  float s = 0.f;
  for (int j=0;j<NL;j++) s += fabsf(p[j]);
  cs[row] = s;
}
__global__ void rowsum_k(const float* __restrict__ a2, float* __restrict__ rs){
  int h = blockIdx.x, j = threadIdx.x;
  float s = 0.f;
  for (int i=0;i<NL;i++) s += fabsf(a2[((long)h*NL + i)*NL + j]);
  rs[h*NL + j] = s;
}
__global__ void maxmul_k(const float* __restrict__ cs, const float* __restrict__ rs,
                         float* __restrict__ sc){
  int tid = threadIdx.x;
  float mc = -3.4e38f, mr = -3.4e38f;
  for (int i = tid; i < NH*NL; i += 256){ mc = fmaxf(mc, cs[i]); mr = fmaxf(mr, rs[i]); }
  __shared__ float sa[8], sb[8];
  mc = warpMax(mc); mr = warpMax(mr);
  if ((tid&31)==0){ sa[tid>>5]=mc; sb[tid>>5]=mr; }
  __syncthreads();
  if (tid < 32){
    float a = (tid<8)? sa[tid] : -3.4e38f;
    float b = (tid<8)? sb[tid] : -3.4e38f;
    a = warpMax(a); b = warpMax(b);
    if (tid==0) sc[0] = a*b;
  }
}

// ---------- persistent pinv ----------
struct PinvSmem { float As[64][40]; float Bs[32][264]; };

__device__ __forceinline__ void head_bar(int* c, int tid){
  __syncthreads();
  if (tid == 0){
    __threadfence();
    atomicAdd(c, 1);
    while (atomicAdd(c, 0) < 4) __nanosleep(32);
    __threadfence();
  }
  __syncthreads();
}

__device__ void pinv_mm(const float* __restrict__ L, const float* __restrict__ R,
                        float* __restrict__ O, int rb, float beta, float alphaD, bool tr,
                        PinvSmem* s)
{
  int tid = threadIdx.x, wid = tid>>5;
  int wm = wid & 1, wn = wid >> 1;
  wmma::fragment<wmma::accumulator,16,16,8,float> acc[2][4];
  #pragma unroll
  for (int im=0;im<2;im++)
    #pragma unroll
    for (int jn=0;jn<4;jn++) wmma::fill_fragment(acc[im][jn], 0.f);

  for (int k0=0; k0<NL; k0+=32){
    #pragma unroll
    for (int i=0;i<2;i++){
      int lin = tid + i*256;
      int r = lin >> 3, k4 = (lin & 7)*4;
      float4 v = __ldcg((const float4*)&L[(long)(rb*64+r)*NL + k0 + k4]);
      *(float4*)&s->As[r][k4] = v;
    }
    #pragma unroll
    for (int i=0;i<8;i++){
      int lin = tid + i*256;
      int kk = lin >> 6, c4 = (lin & 63)*4;
      float4 v = __ldcg((const float4*)&R[(long)(k0+kk)*NL + c4]);
      if (tr){
        int gk = k0 + kk;
        v.x = tf32r(beta*v.x + ((gk==c4  ) ? alphaD : 0.f));
        v.y = tf32r(beta*v.y + ((gk==c4+1) ? alphaD : 0.f));
        v.z = tf32r(beta*v.z + ((gk==c4+2) ? alphaD : 0.f));
        v.w = tf32r(beta*v.w + ((gk==c4+3) ? alphaD : 0.f));
      }
      *(float4*)&s->Bs[kk][c4] = v;
    }
    __syncthreads();
    #pragma unroll
    for (int kk=0; kk<32; kk+=8){
      wmma::fragment<wmma::matrix_a,16,16,8,wmma::precision::tf32,wmma::row_major> af[2];
      wmma::fragment<wmma::matrix_b,16,16,8,wmma::precision::tf32,wmma::row_major> bf[4];
      #pragma unroll
      for (int im=0;im<2;im++)
        wmma::load_matrix_sync(af[im], &s->As[wm*32 + im*16][kk], 40);
      #pragma unroll
      for (int jn=0;jn<4;jn++)
        wmma::load_matrix_sync(bf[jn], &s->Bs[kk][wn*64 + jn*16], 264);
      #pragma unroll
      for (int im=0;im<2;im++)
        #pragma unroll
        for (int jn=0;jn<4;jn++)
          wmma::mma_sync(acc[im][jn], af[im], bf[jn], acc[im][jn]);
    }
    __syncthreads();
  }
  #pragma unroll
  for (int im=0;im<2;im++)
    #pragma unroll
    for (int jn=0;jn<4;jn++){
      #pragma unroll
      for (int e=0;e<acc[im][jn].num_elements;e++)
        acc[im][jn].x[e] = tf32r(acc[im][jn].x[e]);
      wmma::store_matrix_sync(&O[(long)(rb*64 + wm*32 + im*16)*NL + wn*64 + jn*16],
                              acc[im][jn], NL, wmma::mem_row_major);
    }
}

__global__ void pinv_k(const float* __restrict__ a2f, float* __restrict__ zAf,
                       float* __restrict__ zBf, float* __restrict__ xzf,
                       float* __restrict__ ubf, float* __restrict__ tbf,
                       const float* __restrict__ sc, int* __restrict__ cnt)
{
  __shared__ PinvSmem s;
  int rb = blockIdx.x, h = blockIdx.y, tid = threadIdx.x;
  const long HS = (long)h*NL*NL;
  const float* a2 = a2f + HS;
  float* ZA = zAf + HS; float* ZB = zBf + HS;
  float* XZ = xzf + HS; float* UB = ubf + HS; float* TB = tbf + HS;
  int* c = cnt + h*32;

  float inv = 1.f / sc[0];
  for (int idx = tid; idx < 64*NL; idx += 256){
    int i = rb*64 + (idx >> 8), j = idx & 255;
    ZA[(long)i*NL + j] = tf32r(__ldcg(&a2[(long)j*NL + i]) * inv);
  }
  int step = 0;
  head_bar(c + step++, tid);

  float* cur = ZA; float* nxt = ZB;
  for (int it=0; it<6; ++it){
    pinv_mm(a2, cur, XZ, rb, 0.f, 0.f, false, &s);        head_bar(c + step++, tid);
    pinv_mm(XZ, XZ, UB, rb, -1.f, 7.f, true, &s);         head_bar(c + step++, tid);
    pinv_mm(XZ, UB, TB, rb, -1.f, 15.f, true, &s);        head_bar(c + step++, tid);
    pinv_mm(cur, TB, nxt, rb, -0.25f, 3.25f, true, &s);   head_bar(c + step++, tid);
    float* t = cur; cur = nxt; nxt = t;
  }
}

__global__ void a3v_partial_k(const float* __restrict__ a3, const float* __restrict__ qkv,
                              const float* __restrict__ m3, const float* __restrict__ i3,
                              float* __restrict__ part){
  int ch = blockIdx.x, h = blockIdx.y;
  int tid = threadIdx.x;
  __shared__ float a3s[256][33];
  __shared__ float vs[32][DH];
  __shared__ float m3s[256], i3s[256];
  m3s[tid] = m3[h*NL + tid];
  i3s[tid] = i3[h*NL + tid];
  __syncthreads();
  float acc[DH];
  #pragma unroll
  for (int d=0;d<DH;d++) acc[d]=0.f;
  int k0base = ch * (NP/32);
  for (int kk0 = 0; kk0 < NP/32; kk0 += 32) {
    int kbase = k0base + kk0;
    #pragma unroll
    for (int idx = tid; idx < 256*32; idx += 256) {
      int r = idx >> 5, k = idx & 31;
      float raw = a3[((long)h*NL + r)*NP + kbase + k];
      a3s[r][k] = __expf(raw - m3s[r]) * i3s[r];
    }
    #pragma unroll
    for (int idx = tid; idx < 32*DH; idx += 256) {
      int k = idx >> 6, d = idx & 63;
      vs[k][d] = qkv[(long)(kbase+k)*KQKV + 2*CDIM + h*DH + d];
    }
    __syncthreads();
    #pragma unroll 4
    for (int k=0;k<32;k++){
      float pp = a3s[tid][k];
      #pragma unroll
      for (int d=0;d<DH;d++) acc[d] = fmaf(pp, vs[k][d], acc[d]);
    }
    __syncthreads();
  }
  float* o = part + (((long)h*32 + ch)*NL + tid)*DH;
  #pragma unroll
  for (int d=0;d<DH;d++) o[d] = acc[d];
}
__global__ void a3v_reduce_k(const float* __restrict__ part, float* __restrict__ out){
  int idx = blockIdx.x*256 + threadIdx.x;
  int h = idx >> 14;
  int rem = idx & 16383;
  float s = 0.f;
  #pragma unroll
  for (int ch=0; ch<32; ch++)
    s += part[(((long)h*32 + ch) << 14) + rem];
  out[idx] = tf32r(s);
}

// ---- fused: S = q@kl^T ; softmax(0.125*S) ; att += S @ w2 ----
#define SLD 260
__global__ void __launch_bounds__(256,1) a1w2f_k(const float* __restrict__ qkv,
                                                 const float* __restrict__ kl,
                                                 const float* __restrict__ w2,
                                                 float* __restrict__ att){
  extern __shared__ float sm_[];
  float* S  = sm_;                   // [128][SLD]
  float* Q  = sm_ + 128*SLD;         // [128][72]
  float* KL = Q + 128*72;            // [128][72]
  float* W  = Q;                     // [256][72] overlays Q..KL in phase 3
  int tid = threadIdx.x;
  int h = blockIdx.y;
  long rowbase = (long)blockIdx.x*128;
  int wid = tid>>5;

  #pragma unroll
  for (int i=0;i<8;i++){
    int lin = tid + i*256;
    int r = lin >> 4, c4 = (lin & 15)*4;
    float4 v = *(const float4*)&qkv[(rowbase + r)*KQKV + h*DH + c4];
    *(float4*)&Q[r*72 + c4] = v;
  }

  {
    int wm = wid & 3, wn = wid >> 2;
    for (int half=0; half<2; half++){
      #pragma unroll
      for (int i=0;i<8;i++){
        int lin = tid + i*256;
        int r = lin >> 4, c4 = (lin & 15)*4;
        float4 v = *(const float4*)&kl[((long)h*NL + half*128 + r)*DH + c4];
        *(float4*)&KL[r*72 + c4] = v;
      }
      __syncthreads();
      wmma::fragment<wmma::accumulator,16,16,8,float> acc[2][4];
      #pragma unroll
      for (int im=0;im<2;im++)
        #pragma unroll
        for (int jn=0;jn<4;jn++) wmma::fill_fragment(acc[im][jn], 0.f);
      #pragma unroll
      for (int k0=0;k0<DH;k0+=8){
        wmma::fragment<wmma::matrix_a,16,16,8,wmma::precision::tf32,wmma::row_major> af[2];
        wmma::fragment<wmma::matrix_b,16,16,8,wmma::precision::tf32,wmma::col_major> bf[4];
        #pragma unroll
        for (int im=0;im<2;im++)
          wmma::load_matrix_sync(af[im], Q + (wm*32 + im*16)*72 + k0, 72);
        #pragma unroll
        for (int jn=0;jn<4;jn++)
          wmma::load_matrix_sync(bf[jn], KL + (wn*64 + jn*16)*72 + k0, 72);
        #pragma unroll
        for (int im=0;im<2;im++)
          #pragma unroll
          for (int jn=0;jn<4;jn++)
            wmma::mma_sync(acc[im][jn], af[im], bf[jn], acc[im][jn]);
      }
      #pragma unroll
      for (int im=0;im<2;im++)
        #pragma unroll
        for (int jn=0;jn<4;jn++)
          wmma::store_matrix_sync(S + (long)(wm*32 + im*16)*SLD + half*128 + wn*64 + jn*16,
                                  acc[im][jn], SLD, wmma::mem_row_major);
      __syncthreads();
    }
  }

  #pragma unroll
  for (int i=0;i<16;i++){
    int lin = tid + i*256;
    int r = lin >> 4, c4 = (lin & 15)*4;
    float4 v = *(const float4*)&w2[(long)h*NL*DH + r*DH + c4];
    *(float4*)&W[r*72 + c4] = v;
  }
  {
    int r = tid >> 1, hf = tid & 1;
    float* Sr = S + r*SLD + hf*128;
    float m = -3.4e38f;
    #pragma unroll
    for (int j=0;j<128;j++) m = fmaxf(m, Sr[j]);
    m = fmaxf(m, __shfl_xor_sync(0xffffffffu, m, 1));
    float s = 0.f;
    #pragma unroll
    for (int j=0;j<128;j++){ float e = __expf(0.125f*(Sr[j]-m)); Sr[j]=e; s += e; }
    s += __shfl_xor_sync(0xffffffffu, s, 1);
    float inv = 1.f/s;
    #pragma unroll
    for (int j=0;j<128;j++) Sr[j] = tf32r(Sr[j]*inv);
  }
  __syncthreads();

  {
    int wm = wid & 3, wn = wid >> 2;
    wmma::fragment<wmma::accumulator,16,16,8,float> acc[2][2];
    #pragma unroll
    for (int im=0;im<2;im++)
      #pragma unroll
      for (int jn=0;jn<2;jn++)
        wmma::load_matrix_sync(acc[im][jn],
            att + (rowbase + wm*32 + im*16)*CDIM + h*DH + wn*32 + jn*16,
            CDIM, wmma::mem_row_major);
    for (int k0=0;k0<NL;k0+=8){
      wmma::fragment<wmma::matrix_a,16,16,8,wmma::precision::tf32,wmma::row_major> af[2];
      wmma::fragment<wmma::matrix_b,16,16,8,wmma::precision::tf32,wmma::row_major> bf[2];
      #pragma unroll
      for (int im=0;im<2;im++)
        wmma::load_matrix_sync(af[im], S + (wm*32 + im*16)*SLD + k0, SLD);
      #pragma unroll
      for (int jn=0;jn<2;jn++)
        wmma::load_matrix_sync(bf[jn], W + k0*72 + wn*32 + jn*16, 72);
      #pragma unroll
      for (int im=0;im<2;im++)
        #pragma unroll
        for (int jn=0;jn<2;jn++)
          wmma::mma_sync(acc[im][jn], af[im], bf[jn], acc[im][jn]);
    }
    #pragma unroll
    for (int im=0;im<2;im++)
      #pragma unroll
      for (int jn=0;jn<2;jn++){
        #pragma unroll
        for (int e=0;e<acc[im][jn].num_elements;e++)
          acc[im][jn].x[e] = tf32r(acc[im][jn].x[e]);
        wmma::store_matrix_sync(att + (rowbase + wm*32 + im*16)*CDIM + h*DH + wn*32 + jn*16,
                                acc[im][jn], CDIM, wmma::mem_row_major);
      }
  }
}
constexpr int DSM_A1W2F = (128*SLD + 2*128*72)*4;

__global__ void conv_res_k(const float* __restrict__ qkv, const float* __restrict__ rw,
                           float* __restrict__ att){
  int idx = blockIdx.x*256 + threadIdx.x;
  int c  = idx & (CDIM-1);
  int ig = idx >> 9;
  int i0 = ig*8;
  const float* w = rw + (c>>6)*33;
  float wl[33];
  #pragma unroll
  for (int u=0;u<33;u++) wl[u] = w[u];
  float vb[40];
  #pragma unroll
  for (int u=0;u<40;u++){
    int r = i0 - 16 + u;
    vb[u] = (r>=0 && r<NP) ? qkv[(long)r*KQKV + 2*CDIM + c] : 0.f;
  }
  #pragma unroll
  for (int t=0;t<8;t++){
    float acc = 0.f;
    #pragma unroll
    for (int u=0;u<33;u++) acc = fmaf(wl[u], vb[t+u], acc);
    att[(long)(i0+t)*CDIM + c] = acc;
  }
}

__global__ void build_wc_k(const float* __restrict__ w7, const float* __restrict__ w5,
                           const float* __restrict__ w3, float* __restrict__ wc){
  int c = blockIdx.x, k = threadIdx.x;
  int ky = k/7, kx = k%7, dy = ky-3, dx = kx-3;
  float w = w7[c*49 + k];
  if (dy>=-2 && dy<=2 && dx>=-2 && dx<=2) w += w5[c*25 + (dy+2)*5 + (dx+2)];
  if (dy>=-1 && dy<=1 && dx>=-1 && dx<=1) w += w3[c*9  + (dy+1)*3 + (dx+1)];
  if (dy==0 && dx==0) w += 1.f;
  wc[k*CDIM + c] = w;
}

__global__ void cls_copy_k(const float* __restrict__ hin, float* __restrict__ hout){
  hout[threadIdx.x] = hin[threadIdx.x];
  hout[256+threadIdx.x] = hin[256+threadIdx.x];
}

__global__ void ppeg_k(const float* __restrict__ hin, float* __restrict__ hout,
                       const float* __restrict__ wc,
                       const float* __restrict__ b7, const float* __restrict__ b5,
                       const float* __restrict__ b3){
  int bx = blockIdx.x;
  int c  = blockIdx.y*128 + threadIdx.x;
  int y  = bx / 25;
  int xg = (bx % 25) * 4;
  float bsum = b7[c] + b5[c] + b3[c];
  float acc[4] = {bsum, bsum, bsum, bsum};
  #pragma unroll
  for (int ky=0; ky<7; ky++){
    int yy = y + ky - 3;
    bool vy = (yy>=0 && yy<100);
    #pragma unroll
    for (int dx=-3; dx<=6; dx++){
      int xx = xg + dx;
      float v = (vy && xx>=0 && xx<100) ? hin[(long)(1 + yy*100 + xx)*CDIM + c] : 0.f;
      #pragma unroll
      for (int j=0;j<4;j++){
        int kx = dx - j + 3;
        if (kx>=0 && kx<7) acc[j] = fmaf(wc[(ky*7+kx)*CDIM + c], v, acc[j]);
      }
    }
  }
  #pragma unroll
  for (int j=0;j<4;j++)
    hout[(long)(1 + y*100 + xg + j)*CDIM + c] = acc[j];
}

__global__ void addres_k(float* __restrict__ h, const float* __restrict__ tmp,
                         const float* __restrict__ bias){
  long idx = (long)blockIdx.x*256 + threadIdx.x;
  if (idx >= SZ_H) return;
  int c = (int)(idx & (CDIM-1));
  h[idx] += tmp[idx] + bias[c];
}

static void run_attn_block(float* base, float* h,
                           const float* lng, const float* lnb,
                           const float* qkvwR, const float* outwR, const float* outb,
                           const float* resw,
                           cudaStream_t sB, cudaStream_t sC,
                           cudaEvent_t eF, cudaEvent_t eJ, cudaEvent_t eC)
{
  float* lnx  = base + OFF_LNX;
  float* qkv  = base + OFF_QKV;
  float* ql   = base + OFF_QL;
  float* kl   = base + OFF_KL;
  float* a3   = base + OFF_A3;
  float* a2   = base + OFF_A2;
  float* zA   = base + OFF_ZA;
  float* zB   = base + OFF_ZB;
  float* xz   = base + OFF_XZ;
  float* tb   = base + OFF_TB;
  float* ub   = base + OFF_UB;
  float* cs   = base + OFF_CS;
  float* rs   = base + OFF_RS;
  float* sc   = base + OFF_SC;
  float* a3vp = base + OFF_A3VP;
  float* a3v  = base + OFF_A3V;
  float* w2   = base + OFF_W2;
  float* att  = base + OFF_ATT;
  float* tmp  = base + OFF_TMP;
  float* m3   = base + OFF_M3;
  float* i3   = base + OFF_I3;
  int*   cnt  = (int*)(base + OFF_CNT);

  ln_k<true><<<NTOK,128>>>(h, lnx + (long)PADN*CDIM, lng, lnb);

  gemm_tc<128,false,true><<<dim3(KQKV/128, NP/128, 1), 256, DSM_NN128>>>(
      lnx, CDIM, 0, qkvwR, KQKV, 0, qkv, KQKV, 0, NP, KQKV, CDIM, 1.f);

  landmarks_k<<<dim3(NL,NH), DH>>>(qkv, ql, kl);

  cudaEventRecord(eF, 0);
  cudaStreamWaitEvent(sB, eF, 0);
  cudaStreamWaitEvent(sC, eF, 0);

  conv_res_k<<<(NP/8)*CDIM/256, 256, 0, sC>>>(qkv, resw, att);
  cudaEventRecord(eC, sC);

  gemm_tc<128,true,false><<<dim3(2, 2, NH), 256, DSM_NT128, sB>>>(
      ql, DH, (long)NL*DH, kl, DH, (long)NL*DH, a2, NL, (long)NL*NL, NL, NL, DH, 0.125f);
  softmax256<<<NH*NL, 256, 0, sB>>>(a2);
  colsum_k<<<8,256,0,sB>>>(a2, cs);
  rowsum_k<<<8,256,0,sB>>>(a2, rs);
  maxmul_k<<<1,256,0,sB>>>(cs, rs, sc);
  zero_k<<<1,256,0,sB>>>(base + OFF_CNT, 256);
  pinv_k<<<dim3(4,NH), 256, 0, sB>>>(a2, zA, zB, xz, ub, tb, sc, cnt);
  cudaEventRecord(eJ, sB);

  gemm_tc<128,true,false><<<dim3(NP/128, 2, NH), 256, DSM_NT128>>>(
      ql, DH, (long)NL*DH, qkv + CDIM, KQKV, 64, a3, NP, (long)NL*NP, NL, NP, DH, 0.125f);
  rowstat3_k<<<dim3(NL,NH), 256>>>(a3, m3, i3);
  a3v_partial_k<<<dim3(32,NH),256>>>(a3, qkv, m3, i3, a3vp);
  a3v_reduce_k<<<(unsigned)((NH*NL*DH)/256),256>>>(a3vp, a3v);

  cudaStreamWaitEvent(0, eJ, 0);
  gemm_tc<64,false,false><<<dim3(1,2,NH), 256, DSM_NN64>>>(
      zA, NL, (long)NL*NL, a3v, DH, (long)NL*DH, w2, DH, (long)NL*DH, NL, DH, NL, 1.f);

  cudaStreamWaitEvent(0, eC, 0);
  a1w2f_k<<<dim3(NP/128, NH), 256, DSM_A1W2F>>>(qkv, kl, w2, att);

  gemm_tc<128,false,false><<<dim3(CDIM/128, MPAD/128, 1), 256, DSM_NN128>>>(
      att + (long)PADN*CDIM, CDIM, 0, outwR, CDIM, 0, tmp, CDIM, 0, NTOK, CDIM, CDIM, 1.f);
  addres_k<<<(unsigned)((SZ_H+255)/256),256>>>(h, tmp, outb);
}

extern "C" void kernel_launch(void* const* d_in, const int* in_sizes, int n_in,
                              void* d_out, int out_size)
{
  (void)in_sizes; (void)n_in; (void)out_size;
  const float* features = (const float*)d_in[0];
  const float* cls      = (const float*)d_in[1];
  const float* ln1_g    = (const float*)d_in[2];
  const float* ln1_b    = (const float*)d_in[3];
  const float* qkv1_w   = (const float*)d_in[4];
  const float* out1_w   = (const float*)d_in[5];
  const float* out1_b   = (const float*)d_in[6];
  const float* res1_w   = (const float*)d_in[7];
  const float* w7       = (const float*)d_in[8];
  const float* b7       = (const float*)d_in[9];
  const float* w5       = (const float*)d_in[10];
  const float* b5       = (const float*)d_in[11];
  const float* w3       = (const float*)d_in[12];
  const float* b3       = (const float*)d_in[13];
  const float* ln2_g    = (const float*)d_in[14];
  const float* ln2_b    = (const float*)d_in[15];
  const float* qkv2_w   = (const float*)d_in[16];
  const float* out2_w   = (const float*)d_in[17];
  const float* out2_b   = (const float*)d_in[18];
  const float* res2_w   = (const float*)d_in[19];
  const float* lnf_g    = (const float*)d_in[20];
  const float* lnf_b    = (const float*)d_in[21];

  cudaFuncSetAttribute((const void*)gemm_tc<128,false,true>,  cudaFuncAttributeMaxDynamicSharedMemorySize, DSM_NN128);
  cudaFuncSetAttribute((const void*)gemm_tc<128,false,false>, cudaFuncAttributeMaxDynamicSharedMemorySize, DSM_NN128);
  cudaFuncSetAttribute((const void*)gemm_tc<128,true,false>,  cudaFuncAttributeMaxDynamicSharedMemorySize, DSM_NT128);
  cudaFuncSetAttribute((const void*)gemm_tc<64,false,false>,  cudaFuncAttributeMaxDynamicSharedMemorySize, DSM_NN64);
  cudaFuncSetAttribute((const void*)a1w2f_k,                  cudaFuncAttributeMaxDynamicSharedMemorySize, DSM_A1W2F);

  float* base = nullptr;
  cudaGetSymbolAddress((void**)&base, g_scratch);

  static cudaStream_t sB = nullptr, sC = nullptr;
  static cudaEvent_t eF1, eJ1, eC1, eF2, eJ2, eC2;
  if (!sB){
    cudaStreamCreateWithFlags(&sB, cudaStreamNonBlocking);
    cudaStreamCreateWithFlags(&sC, cudaStreamNonBlocking);
    cudaEventCreateWithFlags(&eF1, cudaEventDisableTiming);
    cudaEventCreateWithFlags(&eJ1, cudaEventDisableTiming);
    cudaEventCreateWithFlags(&eC1, cudaEventDisableTiming);
    cudaEventCreateWithFlags(&eF2, cudaEventDisableTiming);
    cudaEventCreateWithFlags(&eJ2, cudaEventDisableTiming);
    cudaEventCreateWithFlags(&eC2, cudaEventDisableTiming);
  }

  float* hA = base + OFF_HA;
  float* hB = base + OFF_HB;

  round_copy_k<<<(unsigned)(((long)CDIM*KQKV+255)/256),256>>>(qkv1_w, base + OFF_W1R, (long)CDIM*KQKV);
  round_copy_k<<<(unsigned)(((long)CDIM*CDIM+255)/256),256>>>(out1_w, base + OFF_O1R, (long)CDIM*CDIM);
  round_copy_k<<<(unsigned)(((long)CDIM*KQKV+255)/256),256>>>(qkv2_w, base + OFF_W2R, (long)CDIM*KQKV);
  round_copy_k<<<(unsigned)(((long)CDIM*CDIM+255)/256),256>>>(out2_w, base + OFF_O2R, (long)CDIM*CDIM);

  init_h_k<<<(unsigned)((SZ_H + 255)/256), 256>>>(features, cls, hA);
  zero_k<<<(unsigned)(((long)PADN*CDIM + 255)/256), 256>>>(base + OFF_LNX, (long)PADN*CDIM);

  run_attn_block(base, hA, ln1_g, ln1_b, base + OFF_W1R, base + OFF_O1R, out1_b, res1_w,
                 sB, sC, eF1, eJ1, eC1);

  build_wc_k<<<CDIM, 49>>>(w7, w5, w3, base + OFF_WC);
  cls_copy_k<<<1,256>>>(hA, hB);
  ppeg_k<<<dim3(2500, 4), 128>>>(hA, hB, base + OFF_WC, b7, b5, b3);

  run_attn_block(base, hB, ln2_g, ln2_b, base + OFF_W2R, base + OFF_O2R, out2_b, res2_w,
                 sB, sC, eF2, eJ2, eC2);

  ln_k<false><<<NTOK, 128>>>(hB, (float*)d_out, lnf_g, lnf_b);
}

// round 15
// speedup vs baseline: 1.2655x; 1.2655x over previous
#include <cuda_runtime.h>
#include <cuda_fp16.h>
#include <cstdint>
#include <mma.h>
using namespace nvcuda;

#define NTOK 10001
#define CDIM 512
#define NP   10240
#define PADN 239
#define NH   8
#define DH   64
#define NL   256
#define LW   40
#define KQKV (3*CDIM)
#define MPAD 10112

constexpr long SZ_H    = (long)NTOK*CDIM;
constexpr long SZ_LNX  = (long)NP*CDIM;
constexpr long SZ_QKV  = (long)NP*KQKV;
constexpr long SZ_LAND = (long)NH*NL*DH;
constexpr long SZ_A1   = (long)NH*NP*NL;
constexpr long SZ_A2   = (long)NH*NL*NL;

constexpr long OFF_HA   = 0;
constexpr long OFF_HB   = OFF_HA  + SZ_H;
constexpr long OFF_LNX  = OFF_HB  + SZ_H;      // half[NP*CDIM]
constexpr long OFF_QKV  = OFF_LNX + SZ_LNX;    // half[NP*KQKV]
constexpr long OFF_QL   = OFF_QKV + SZ_QKV;    // half
constexpr long OFF_KL   = OFF_QL  + SZ_LAND;   // half
constexpr long OFF_A1   = OFF_KL  + SZ_LAND;   // reused: zAh (half) + atth (half)
constexpr long OFF_ZAH  = OFF_A1;
constexpr long OFF_ATTH = OFF_A1  + SZ_A2;     // half[NP*CDIM]
constexpr long OFF_A3   = OFF_A1  + SZ_A1;
constexpr long OFF_A2   = OFF_A3  + SZ_A1;
constexpr long OFF_ZA   = OFF_A2  + SZ_A2;
constexpr long OFF_ZB   = OFF_ZA  + SZ_A2;
constexpr long OFF_XZ   = OFF_ZB  + SZ_A2;
constexpr long OFF_TB   = OFF_XZ  + SZ_A2;
constexpr long OFF_UB   = OFF_TB  + SZ_A2;
constexpr long OFF_CS   = OFF_UB  + SZ_A2;
constexpr long OFF_RS   = OFF_CS  + 2048;
constexpr long OFF_SC   = OFF_RS  + 2048;
constexpr long OFF_A3VP = OFF_SC  + 8;
constexpr long SZ_A3VP  = (long)NH*32*NL*DH;
constexpr long OFF_A3V  = OFF_A3VP + SZ_A3VP;  // half
constexpr long OFF_W2   = OFF_A3V + SZ_LAND;   // float
constexpr long OFF_ATT  = OFF_W2  + SZ_LAND;   // float[NP*CDIM]
constexpr long OFF_TMP  = OFF_ATT + SZ_LNX;
constexpr long OFF_WC   = OFF_TMP + (long)MPAD*CDIM;
constexpr long OFF_CNT  = OFF_WC + 512*49;
constexpr long OFF_W1R  = OFF_CNT + 256;       // half
constexpr long OFF_O1R  = OFF_W1R + (long)CDIM*KQKV;
constexpr long OFF_W2R  = OFF_O1R + (long)CDIM*CDIM;
constexpr long OFF_O2R  = OFF_W2R + (long)CDIM*KQKV;
constexpr long OFF_M3   = OFF_O2R + (long)CDIM*CDIM;
constexpr long OFF_I3   = OFF_M3 + 2048;
constexpr long SCRATCH_SZ = OFF_I3 + 2048 + 64;

static __device__ float g_scratch[SCRATCH_SZ];

__device__ __forceinline__ float tf32r(float x){
  unsigned int u;
  asm("cvt.rna.tf32.f32 %0, %1;\n" : "=r"(u) : "f"(x));
  return __uint_as_float(u);
}

__device__ __forceinline__ float warpMax(float v){
  #pragma unroll
  for (int o=16;o;o>>=1) v = fmaxf(v, __shfl_xor_sync(0xffffffffu, v, o));
  return v;
}
__device__ __forceinline__ float warpSum(float v){
  #pragma unroll
  for (int o=16;o;o>>=1) v += __shfl_xor_sync(0xffffffffu, v, o);
  return v;
}

__device__ __forceinline__ void cp16g(void* dst, const void* src, bool ok){
  unsigned int d = (unsigned int)__cvta_generic_to_shared(dst);
  int b = ok ? 16 : 0;
  asm volatile("cp.async.cg.shared.global [%0], [%1], 16, %2;\n" :: "r"(d), "l"(src), "r"(b));
}

__global__ void roundh_copy_k(const float* __restrict__ in, __half* __restrict__ out, long n){
  long i = (long)blockIdx.x*256 + threadIdx.x;
  if (i < n) out[i] = __float2half_rn(in[i]);
}

__global__ void f2h_k(const float* __restrict__ in, __half* __restrict__ out, long n){
  long i = (long)blockIdx.x*256 + threadIdx.x;
  if (i < n) out[i] = __float2half_rn(in[i]);
}

__global__ void init_h_k(const float* __restrict__ feat, const float* __restrict__ cls,
                         float* __restrict__ h){
  long i = (long)blockIdx.x*256 + threadIdx.x;
  if (i >= SZ_H) return;
  h[i] = (i < CDIM) ? cls[i] : feat[i - CDIM];
}

__global__ void zero_k(float* __restrict__ p, long n){
  long i = (long)blockIdx.x*256 + threadIdx.x;
  if (i < n) p[i] = 0.f;
}

// LN writing half
__global__ void ln_h_k(const float* __restrict__ x, __half* __restrict__ y,
                       const float* __restrict__ g, const float* __restrict__ b){
  const int t = blockIdx.x;
  const float* xr = x + (long)t*CDIM;
  __half* yr = y + (long)t*CDIM;
  int tid = threadIdx.x;
  float s = 0.f, s2 = 0.f;
  #pragma unroll
  for (int c = tid; c < CDIM; c += 128){ float v = xr[c]; s += v; s2 += v*v; }
  #pragma unroll
  for (int o=16;o;o>>=1){ s += __shfl_xor_sync(0xffffffffu,s,o); s2 += __shfl_xor_sync(0xffffffffu,s2,o); }
  __shared__ float sm[4], sm2[4];
  if ((tid&31)==0){ sm[tid>>5]=s; sm2[tid>>5]=s2; }
  __syncthreads();
  s  = sm[0]+sm[1]+sm[2]+sm[3];
  s2 = sm2[0]+sm2[1]+sm2[2]+sm2[3];
  float mu  = s * (1.f/CDIM);
  float var = s2 * (1.f/CDIM) - mu*mu;
  float inv = rsqrtf(var + 1e-5f);
  #pragma unroll
  for (int c = tid; c < CDIM; c += 128)
    yr[c] = __float2half_rn((xr[c]-mu)*inv*g[c] + b[c]);
}

// final LN, float out
__global__ void ln_k(const float* __restrict__ x, float* __restrict__ y,
                     const float* __restrict__ g, const float* __restrict__ b){
  const int t = blockIdx.x;
  const float* xr = x + (long)t*CDIM;
  float* yr = y + (long)t*CDIM;
  int tid = threadIdx.x;
  float s = 0.f, s2 = 0.f;
  #pragma unroll
  for (int c = tid; c < CDIM; c += 128){ float v = xr[c]; s += v; s2 += v*v; }
  #pragma unroll
  for (int o=16;o;o>>=1){ s += __shfl_xor_sync(0xffffffffu,s,o); s2 += __shfl_xor_sync(0xffffffffu,s2,o); }
  __shared__ float sm[4], sm2[4];
  if ((tid&31)==0){ sm[tid>>5]=s; sm2[tid>>5]=s2; }
  __syncthreads();
  s  = sm[0]+sm[1]+sm[2]+sm[3];
  s2 = sm2[0]+sm2[1]+sm2[2]+sm2[3];
  float mu  = s * (1.f/CDIM);
  float var = s2 * (1.f/CDIM) - mu*mu;
  float inv = rsqrtf(var + 1e-5f);
  #pragma unroll
  for (int c = tid; c < CDIM; c += 128)
    yr[c] = (xr[c]-mu)*inv*g[c] + b[c];
}

// ---------- fp16 tensor-core GEMM, fp32 accumulate, 2-stage cp.async ----------
// NT: B stored [N,K]. HOUT: write C as half (via smem staging); else float.
template<int BN, bool NT, bool HOUT>
__global__ void __launch_bounds__(256,2) gemm16(
                        const __half* __restrict__ A, int lda, long sA,
                        const __half* __restrict__ B, int ldb, long sB,
                        void* __restrict__ Cv, int ldc, long sC,
                        int M, int N, int K, float alpha)
{
  constexpr int BM=128, BK=32, BKP=40, BNPH=BN+8;
  constexpr int WN = BN/2, NF = WN/16;
  constexpr int ASZ = BM*BKP;                  // halves
  constexpr int BSZ = NT ? BN*BKP : BK*BNPH;   // halves
  extern __shared__ __half dynh[];
  __half* Asm = dynh;
  __half* Bsm = dynh + 2*ASZ;

  const int tid = threadIdx.x;
  const int wid = tid >> 5;
  const int warp_m = wid & 3, warp_n = wid >> 2;
  const int bm = blockIdx.y*BM, bn = blockIdx.x*BN;
  A += (long)blockIdx.z * sA;
  B += (long)blockIdx.z * sB;

  wmma::fragment<wmma::accumulator,16,16,16,float> acc[2][NF];
  #pragma unroll
  for (int im=0;im<2;im++)
    #pragma unroll
    for (int jn=0;jn<NF;jn++) wmma::fill_fragment(acc[im][jn], 0.f);

  auto loadA = [&](int s, int k0){
    __half* As = Asm + s*ASZ;
    #pragma unroll
    for (int i=0;i<2;i++){                     // 128*32/8 = 512 chunks
      int lin = tid + i*256;
      int r = lin >> 2, k8 = (lin & 3)*8;
      int gr = bm + r;
      bool ok = gr < M;
      const __half* src = A + (long)(ok ? gr : bm)*lda + k0 + k8;
      cp16g(As + r*BKP + k8, src, ok);
    }
  };
  auto loadB = [&](int s, int k0){
    __half* Bs = Bsm + s*BSZ;
    if (!NT){
      constexpr int NCH = (BK*BN/8)/256;       // BN=128:2, BN=64:1
      #pragma unroll
      for (int i=0;i<NCH;i++){
        int lin = tid + i*256;
        int kk = lin / (BN/8), c8 = (lin % (BN/8))*8;
        cp16g(Bs + kk*BNPH + c8, B + (long)(k0+kk)*ldb + bn + c8, true);
      }
    } else {
      constexpr int NCH = (BN*BK/8)/256;
      #pragma unroll
      for (int i=0;i<NCH;i++){
        int lin = tid + i*256;
        int c = lin >> 2, k8 = (lin & 3)*8;
        cp16g(Bs + c*BKP + k8, B + (long)(bn+c)*ldb + k0 + k8, true);
      }
    }
  };

  const int nt = K/BK;
  loadA(0, 0); loadB(0, 0);
  asm volatile("cp.async.commit_group;\n");
  for (int t=0; t<nt; t++){
    int cs = t & 1;
    if (t+1 < nt){
      loadA((t+1)&1, (t+1)*BK);
      loadB((t+1)&1, (t+1)*BK);
      asm volatile("cp.async.commit_group;\n");
      asm volatile("cp.async.wait_group 1;\n");
    } else {
      asm volatile("cp.async.wait_group 0;\n");
    }
    __syncthreads();
    __half* As = Asm + cs*ASZ;
    __half* Bs = Bsm + cs*BSZ;
    #pragma unroll
    for (int kk=0; kk<BK; kk+=16){
      wmma::fragment<wmma::matrix_a,16,16,16,__half,wmma::row_major> af[2];
      #pragma unroll
      for (int im=0;im<2;im++)
        wmma::load_matrix_sync(af[im], As + (warp_m*32 + im*16)*BKP + kk, BKP);
      if (!NT){
        wmma::fragment<wmma::matrix_b,16,16,16,__half,wmma::row_major> bf[NF];
        #pragma unroll
        for (int jn=0;jn<NF;jn++)
          wmma::load_matrix_sync(bf[jn], Bs + kk*BNPH + warp_n*WN + jn*16, BNPH);
        #pragma unroll
        for (int im=0;im<2;im++)
          #pragma unroll
          for (int jn=0;jn<NF;jn++)
            wmma::mma_sync(acc[im][jn], af[im], bf[jn], acc[im][jn]);
      } else {
        wmma::fragment<wmma::matrix_b,16,16,16,__half,wmma::col_major> bf[NF];
        #pragma unroll
        for (int jn=0;jn<NF;jn++)
          wmma::load_matrix_sync(bf[jn], Bs + (warp_n*WN + jn*16)*BKP + kk, BKP);
        #pragma unroll
        for (int im=0;im<2;im++)
          #pragma unroll
          for (int jn=0;jn<NF;jn++)
            wmma::mma_sync(acc[im][jn], af[im], bf[jn], acc[im][jn]);
      }
    }
    __syncthreads();
  }
  #pragma unroll
  for (int im=0;im<2;im++)
    #pragma unroll
    for (int jn=0;jn<NF;jn++)
      #pragma unroll
      for (int e=0;e<acc[im][jn].num_elements;e++)
        acc[im][jn].x[e] *= alpha;

  if (!HOUT){
    float* C = (float*)Cv + (long)blockIdx.z * sC;
    #pragma unroll
    for (int im=0;im<2;im++)
      #pragma unroll
      for (int jn=0;jn<NF;jn++){
        int gr = bm + warp_m*32 + im*16;
        if (gr < M)
          wmma::store_matrix_sync(C + (long)gr*ldc + bn + warp_n*WN + jn*16,
                                  acc[im][jn], ldc, wmma::mem_row_major);
      }
  } else {
    // staged half store: two 64-row phases through smem
    __half* C = (__half*)Cv + (long)blockIdx.z * sC;
    float* stg = (float*)dynh;                  // 64 x (BN+4) floats
    constexpr int BNP4 = BN+4;
    __syncthreads();
    #pragma unroll
    for (int phase=0; phase<2; phase++){
      if ((warp_m >> 1) == phase){
        int rloc = (warp_m & 1)*32;
        #pragma unroll
        for (int im=0;im<2;im++)
          #pragma unroll
          for (int jn=0;jn<NF;jn++)
            wmma::store_matrix_sync(stg + (rloc + im*16)*BNP4 + warp_n*WN + jn*16,
                                    acc[im][jn], BNP4, wmma::mem_row_major);
      }
      __syncthreads();
      constexpr int NCH = (64*BN/8)/256;
      #pragma unroll
      for (int i=0;i<NCH;i++){
        int lin = tid + i*256;
        int r = lin / (BN/8), c8 = (lin % (BN/8))*8;
        int gr = bm + phase*64 + r;
        if (gr < M){
          const float* sp = stg + r*BNP4 + c8;
          __half2 h0 = __floats2half2_rn(sp[0], sp[1]);
          __half2 h1 = __floats2half2_rn(sp[2], sp[3]);
          __half2 h2 = __floats2half2_rn(sp[4], sp[5]);
          __half2 h3 = __floats2half2_rn(sp[6], sp[7]);
          __half2* dp = (__half2*)(C + (long)gr*ldc + bn + c8);
          dp[0]=h0; dp[1]=h1; dp[2]=h2; dp[3]=h3;
        }
      }
      __syncthreads();
    }
  }
}

constexpr int DSM16_NN128 = (2*(128*40) + 2*(32*136))*2;
constexpr int DSM16_NT128 = (2*(128*40) + 2*(128*40))*2;
constexpr int DSM16_NN64  = (2*(128*40) + 2*(32*72))*2;

__global__ void landmarks_k(const __half* __restrict__ qkv,
                            __half* __restrict__ ql, __half* __restrict__ kl){
  int j = blockIdx.x, h = blockIdx.y, d = threadIdx.x;
  const __half* base = qkv + (long)(j*LW)*KQKV + h*DH + d;
  float sq = 0.f, sk = 0.f;
  #pragma unroll 8
  for (int t=0;t<LW;t++){
    sq += __half2float(base[(long)t*KQKV]);
    sk += __half2float(base[(long)t*KQKV + CDIM]);
  }
  long o = ((long)h*NL + j)*DH + d;
  ql[o] = __float2half_rn(sq * (1.f/LW));
  kl[o] = __float2half_rn(sk * (1.f/LW));
}

__global__ void softmax256(float* __restrict__ x){
  float* p = x + (long)blockIdx.x * NL;
  int tid = threadIdx.x;
  float v = p[tid];
  __shared__ float sm[8];
  float m = warpMax(v);
  if ((tid&31)==0) sm[tid>>5]=m;
  __syncthreads();
  if (tid < 32){ float t = (tid<8)? sm[tid] : -3.4e38f; t = warpMax(t); if (tid==0) sm[0]=t; }
  __syncthreads();
  m = sm[0];
  __syncthreads();
  float e = __expf(v - m);
  float s = warpSum(e);
  if ((tid&31)==0) sm[tid>>5]=s;
  __syncthreads();
  if (tid < 32){ float t = (tid<8)? sm[tid] : 0.f; t = warpSum(t); if (tid==0) sm[0]=t; }
  __syncthreads();
  p[tid] = tf32r(e / sm[0]);
}

__global__ void rowstat3_k(const float* __restrict__ a3, float* __restrict__ m3,
                           float* __restrict__ i3){
  int r = blockIdx.x, h = blockIdx.y, tid = threadIdx.x;
  const float* p = a3 + ((long)h*NL + r)*NP;
  float va[NP/256];
  float m = -3.4e38f;
  #pragma unroll
  for (int i=0;i<NP/256;i++){ va[i] = p[tid + i*256]; m = fmaxf(m, va[i]); }
  __shared__ float sm[8];
  m = warpMax(m);
  if ((tid&31)==0) sm[tid>>5]=m;
  __syncthreads();
  if (tid < 32){ float t = (tid<8)? sm[tid] : -3.4e38f; t = warpMax(t); if (tid==0) sm[0]=t; }
  __syncthreads();
  m = sm[0];
  __syncthreads();
  float s = 0.f;
  #pragma unroll
  for (int i=0;i<NP/256;i++) s += __expf(va[i]-m);
  s = warpSum(s);
  if ((tid&31)==0) sm[tid>>5]=s;
  __syncthreads();
  if (tid < 32){ float t = (tid<8)? sm[tid] : 0.f; t = warpSum(t); if (tid==0) sm[0]=t; }
  __syncthreads();
  if (tid==0){ m3[h*NL+r]=m; i3[h*NL+r]=1.f/sm[0]; }
}

__global__ void colsum_k(const float* __restrict__ a2, float* __restrict__ cs){
  int row = blockIdx.x*256 + threadIdx.x;
  const float* p = a2 + (long)row*NL;
  float s = 0.f;
  for (int j=0;j<NL;j++) s += fabsf(p[j]);
  cs[row] = s;
}
__global__ void rowsum_k(const float* __restrict__ a2, float* __restrict__ rs){
  int h = blockIdx.x, j = threadIdx.x;
  float s = 0.f;
  for (int i=0;i<NL;i++) s += fabsf(a2[((long)h*NL + i)*NL + j]);
  rs[h*NL + j] = s;
}
__global__ void maxmul_k(const float* __restrict__ cs, const float* __restrict__ rs,
                         float* __restrict__ sc){
  int tid = threadIdx.x;
  float mc = -3.4e38f, mr = -3.4e38f;
  for (int i = tid; i < NH*NL; i += 256){ mc = fmaxf(mc, cs[i]); mr = fmaxf(mr, rs[i]); }
  __shared__ float sa[8], sb[8];
  mc = warpMax(mc); mr = warpMax(mr);
  if ((tid&31)==0){ sa[tid>>5]=mc; sb[tid>>5]=mr; }
  __syncthreads();
  if (tid < 32){
    float a = (tid<8)? sa[tid] : -3.4e38f;
    float b = (tid<8)? sb[tid] : -3.4e38f;
    a = warpMax(a); b = warpMax(b);
    if (tid==0) sc[0] = a*b;
  }
}

// ---------- persistent pinv (tf32, unchanged) ----------
struct PinvSmem { float As[64][40]; float Bs[32][264]; };

__device__ __forceinline__ void head_bar(int* c, int tid){
  __syncthreads();
  if (tid == 0){
    __threadfence();
    atomicAdd(c, 1);
    while (atomicAdd(c, 0) < 4) __nanosleep(32);
    __threadfence();
  }
  __syncthreads();
}

__device__ void pinv_mm(const float* __restrict__ L, const float* __restrict__ R,
                        float* __restrict__ O, int rb, float beta, float alphaD, bool tr,
                        PinvSmem* s)
{
  int tid = threadIdx.x, wid = tid>>5;
  int wm = wid & 1, wn = wid >> 1;
  wmma::fragment<wmma::accumulator,16,16,8,float> acc[2][4];
  #pragma unroll
  for (int im=0;im<2;im++)
    #pragma unroll
    for (int jn=0;jn<4;jn++) wmma::fill_fragment(acc[im][jn], 0.f);

  for (int k0=0; k0<NL; k0+=32){
    #pragma unroll
    for (int i=0;i<2;i++){
      int lin = tid + i*256;
      int r = lin >> 3, k4 = (lin & 7)*4;
      float4 v = __ldcg((const float4*)&L[(long)(rb*64+r)*NL + k0 + k4]);
      *(float4*)&s->As[r][k4] = v;
    }
    #pragma unroll
    for (int i=0;i<8;i++){
      int lin = tid + i*256;
      int kk = lin >> 6, c4 = (lin & 63)*4;
      float4 v = __ldcg((const float4*)&R[(long)(k0+kk)*NL + c4]);
      if (tr){
        int gk = k0 + kk;
        v.x = tf32r(beta*v.x + ((gk==c4  ) ? alphaD : 0.f));
        v.y = tf32r(beta*v.y + ((gk==c4+1) ? alphaD : 0.f));
        v.z = tf32r(beta*v.z + ((gk==c4+2) ? alphaD : 0.f));
        v.w = tf32r(beta*v.w + ((gk==c4+3) ? alphaD : 0.f));
      }
      *(float4*)&s->Bs[kk][c4] = v;
    }
    __syncthreads();
    #pragma unroll
    for (int kk=0; kk<32; kk+=8){
      wmma::fragment<wmma::matrix_a,16,16,8,wmma::precision::tf32,wmma::row_major> af[2];
      wmma::fragment<wmma::matrix_b,16,16,8,wmma::precision::tf32,wmma::row_major> bf[4];
      #pragma unroll
      for (int im=0;im<2;im++)
        wmma::load_matrix_sync(af[im], &s->As[wm*32 + im*16][kk], 40);
      #pragma unroll
      for (int jn=0;jn<4;jn++)
        wmma::load_matrix_sync(bf[jn], &s->Bs[kk][wn*64 + jn*16], 264);
      #pragma unroll
      for (int im=0;im<2;im++)
        #pragma unroll
        for (int jn=0;jn<4;jn++)
          wmma::mma_sync(acc[im][jn], af[im], bf[jn], acc[im][jn]);
    }
    __syncthreads();
  }
  #pragma unroll
  for (int im=0;im<2;im++)
    #pragma unroll
    for (int jn=0;jn<4;jn++){
      #pragma unroll
      for (int e=0;e<acc[im][jn].num_elements;e++)
        acc[im][jn].x[e] = tf32r(acc[im][jn].x[e]);
      wmma::store_matrix_sync(&O[(long)(rb*64 + wm*32 + im*16)*NL + wn*64 + jn*16],
                              acc[im][jn], NL, wmma::mem_row_major);
    }
}

__global__ void pinv_k(const float* __restrict__ a2f, float* __restrict__ zAf,
                       float* __restrict__ zBf, float* __restrict__ xzf,
                       float* __restrict__ ubf, float* __restrict__ tbf,
                       const float* __restrict__ sc, int* __restrict__ cnt)
{
  __shared__ PinvSmem s;
  int rb = blockIdx.x, h = blockIdx.y, tid = threadIdx.x;
  const long HS = (long)h*NL*NL;
  const float* a2 = a2f + HS;
  float* ZA = zAf + HS; float* ZB = zBf + HS;
  float* XZ = xzf + HS; float* UB = ubf + HS; float* TB = tbf + HS;
  int* c = cnt + h*32;

  float inv = 1.f / sc[0];
  for (int idx = tid; idx < 64*NL; idx += 256){
    int i = rb*64 + (idx >> 8), j = idx & 255;
    ZA[(long)i*NL + j] = tf32r(__ldcg(&a2[(long)j*NL + i]) * inv);
  }
  int step = 0;
  head_bar(c + step++, tid);

  float* cur = ZA; float* nxt = ZB;
  for (int it=0; it<6; ++it){
    pinv_mm(a2, cur, XZ, rb, 0.f, 0.f, false, &s);        head_bar(c + step++, tid);
    pinv_mm(XZ, XZ, UB, rb, -1.f, 7.f, true, &s);         head_bar(c + step++, tid);
    pinv_mm(XZ, UB, TB, rb, -1.f, 15.f, true, &s);        head_bar(c + step++, tid);
    pinv_mm(cur, TB, nxt, rb, -0.25f, 3.25f, true, &s);   head_bar(c + step++, tid);
    float* t = cur; cur = nxt; nxt = t;
  }
}

// a3v with softmax folded in; v read as half
__global__ void a3v_partial_k(const float* __restrict__ a3, const __half* __restrict__ qkv,
                              const float* __restrict__ m3, const float* __restrict__ i3,
                              float* __restrict__ part){
  int ch = blockIdx.x, h = blockIdx.y;
  int tid = threadIdx.x;
  __shared__ float a3s[256][33];
  __shared__ float vs[32][DH];
  __shared__ float m3s[256], i3s[256];
  m3s[tid] = m3[h*NL + tid];
  i3s[tid] = i3[h*NL + tid];
  __syncthreads();
  float acc[DH];
  #pragma unroll
  for (int d=0;d<DH;d++) acc[d]=0.f;
  int k0base = ch * (NP/32);
  for (int kk0 = 0; kk0 < NP/32; kk0 += 32) {
    int kbase = k0base + kk0;
    #pragma unroll
    for (int idx = tid; idx < 256*32; idx += 256) {
      int r = idx >> 5, k = idx & 31;
      float raw = a3[((long)h*NL + r)*NP + kbase + k];
      a3s[r][k] = __expf(raw - m3s[r]) * i3s[r];
    }
    #pragma unroll
    for (int idx = tid; idx < 32*DH; idx += 256) {
      int k = idx >> 6, d = idx & 63;
      vs[k][d] = __half2float(qkv[(long)(kbase+k)*KQKV + 2*CDIM + h*DH + d]);
    }
    __syncthreads();
    #pragma unroll 4
    for (int k=0;k<32;k++){
      float pp = a3s[tid][k];
      #pragma unroll
      for (int d=0;d<DH;d++) acc[d] = fmaf(pp, vs[k][d], acc[d]);
    }
    __syncthreads();
  }
  float* o = part + (((long)h*32 + ch)*NL + tid)*DH;
  #pragma unroll
  for (int d=0;d<DH;d++) o[d] = acc[d];
}
__global__ void a3v_reduce_k(const float* __restrict__ part, __half* __restrict__ out){
  int idx = blockIdx.x*256 + threadIdx.x;
  int h = idx >> 14;
  int rem = idx & 16383;
  float s = 0.f;
  #pragma unroll
  for (int ch=0; ch<32; ch++)
    s += part[(((long)h*32 + ch) << 14) + rem];
  out[idx] = __float2half_rn(s);
}

// ---- fused: S = q@kl^T ; softmax(0.125*S) ; att += S @ w2 (tf32 internals, half inputs) ----
#define SLD 260
__global__ void __launch_bounds__(256,1) a1w2f_k(const __half* __restrict__ qkv,
                                                 const __half* __restrict__ kl,
                                                 const float* __restrict__ w2,
                                                 float* __restrict__ att){
  extern __shared__ float sm_[];
  float* S  = sm_;                   // [128][SLD]
  float* Q  = sm_ + 128*SLD;         // [128][72]
  float* KL = Q + 128*72;            // [128][72]
  float* W  = Q;                     // [256][72] overlays Q..KL in phase 3
  int tid = threadIdx.x;
  int h = blockIdx.y;
  long rowbase = (long)blockIdx.x*128;
  int wid = tid>>5;

  #pragma unroll
  for (int i=0;i<4;i++){
    int lin = tid + i*256;
    int r = lin >> 3, c8 = (lin & 7)*8;
    const __half2* sp = (const __half2*)(qkv + (rowbase + r)*KQKV + h*DH + c8);
    float* dp = Q + r*72 + c8;
    #pragma unroll
    for (int u=0;u<4;u++){ float2 f = __half22float2(sp[u]); dp[2*u]=f.x; dp[2*u+1]=f.y; }
  }

  {
    int wm = wid & 3, wn = wid >> 2;
    for (int half_=0; half_<2; half_++){
      #pragma unroll
      for (int i=0;i<4;i++){
        int lin = tid + i*256;
        int r = lin >> 3, c8 = (lin & 7)*8;
        const __half2* sp = (const __half2*)(kl + ((long)h*NL + half_*128 + r)*DH + c8);
        float* dp = KL + r*72 + c8;
        #pragma unroll
        for (int u=0;u<4;u++){ float2 f = __half22float2(sp[u]); dp[2*u]=f.x; dp[2*u+1]=f.y; }
      }
      __syncthreads();
      wmma::fragment<wmma::accumulator,16,16,8,float> acc[2][4];
      #pragma unroll
      for (int im=0;im<2;im++)
        #pragma unroll
        for (int jn=0;jn<4;jn++) wmma::fill_fragment(acc[im][jn], 0.f);
      #pragma unroll
      for (int k0=0;k0<DH;k0+=8){
        wmma::fragment<wmma::matrix_a,16,16,8,wmma::precision::tf32,wmma::row_major> af[2];
        wmma::fragment<wmma::matrix_b,16,16,8,wmma::precision::tf32,wmma::col_major> bf[4];
        #pragma unroll
        for (int im=0;im<2;im++)
          wmma::load_matrix_sync(af[im], Q + (wm*32 + im*16)*72 + k0, 72);
        #pragma unroll
        for (int jn=0;jn<4;jn++)
          wmma::load_matrix_sync(bf[jn], KL + (wn*64 + jn*16)*72 + k0, 72);
        #pragma unroll
        for (int im=0;im<2;im++)
          #pragma unroll
          for (int jn=0;jn<4;jn++)
            wmma::mma_sync(acc[im][jn], af[im], bf[jn], acc[im][jn]);
      }
      #pragma unroll
      for (int im=0;im<2;im++)
        #pragma unroll
        for (int jn=0;jn<4;jn++)
          wmma::store_matrix_sync(S + (long)(wm*32 + im*16)*SLD + half_*128 + wn*64 + jn*16,
                                  acc[im][jn], SLD, wmma::mem_row_major);
      __syncthreads();
    }
  }

  #pragma unroll
  for (int i=0;i<16;i++){
    int lin = tid + i*256;
    int r = lin >> 4, c4 = (lin & 15)*4;
    float4 v = *(const float4*)&w2[(long)h*NL*DH + r*DH + c4];
    *(float4*)&W[r*72 + c4] = v;
  }
  {
    int r = tid >> 1, hf = tid & 1;
    float* Sr = S + r*SLD + hf*128;
    float m = -3.4e38f;
    #pragma unroll
    for (int j=0;j<128;j++) m = fmaxf(m, Sr[j]);
    m = fmaxf(m, __shfl_xor_sync(0xffffffffu, m, 1));
    float s = 0.f;
    #pragma unroll
    for (int j=0;j<128;j++){ float e = __expf(0.125f*(Sr[j]-m)); Sr[j]=e; s += e; }
    s += __shfl_xor_sync(0xffffffffu, s, 1);
    float inv = 1.f/s;
    #pragma unroll
    for (int j=0;j<128;j++) Sr[j] = tf32r(Sr[j]*inv);
  }
  __syncthreads();

  {
    int wm = wid & 3, wn = wid >> 2;
    wmma::fragment<wmma::accumulator,16,16,8,float> acc[2][2];
    #pragma unroll
    for (int im=0;im<2;im++)
      #pragma unroll
      for (int jn=0;jn<2;jn++)
        wmma::load_matrix_sync(acc[im][jn],
            att + (rowbase + wm*32 + im*16)*CDIM + h*DH + wn*32 + jn*16,
            CDIM, wmma::mem_row_major);
    for (int k0=0;k0<NL;k0+=8){
      wmma::fragment<wmma::matrix_a,16,16,8,wmma::precision::tf32,wmma::row_major> af[2];
      wmma::fragment<wmma::matrix_b,16,16,8,wmma::precision::tf32,wmma::row_major> bf[2];
      #pragma unroll
      for (int im=0;im<2;im++)
        wmma::load_matrix_sync(af[im], S + (wm*32 + im*16)*SLD + k0, SLD);
      #pragma unroll
      for (int jn=0;jn<2;jn++)
        wmma::load_matrix_sync(bf[jn], W + k0*72 + wn*32 + jn*16, 72);
      #pragma unroll
      for (int im=0;im<2;im++)
        #pragma unroll
        for (int jn=0;jn<2;jn++)
          wmma::mma_sync(acc[im][jn], af[im], bf[jn], acc[im][jn]);
    }
    #pragma unroll
    for (int im=0;im<2;im++)
      #pragma unroll
      for (int jn=0;jn<2;jn++)
        wmma::store_matrix_sync(att + (rowbase + wm*32 + im*16)*CDIM + h*DH + wn*32 + jn*16,
                                acc[im][jn], CDIM, wmma::mem_row_major);
  }
}
constexpr int DSM_A1W2F = (128*SLD + 2*128*72)*4;

// conv initializes att (fp32), v read as half
__global__ void conv_res_k(const __half* __restrict__ qkv, const float* __restrict__ rw,
                           float* __restrict__ att){
  int idx = blockIdx.x*256 + threadIdx.x;
  int c  = idx & (CDIM-1);
  int ig = idx >> 9;
  int i0 = ig*8;
  const float* w = rw + (c>>6)*33;
  float wl[33];
  #pragma unroll
  for (int u=0;u<33;u++) wl[u] = w[u];
  float vb[40];
  #pragma unroll
  for (int u=0;u<40;u++){
    int r = i0 - 16 + u;
    vb[u] = (r>=0 && r<NP) ? __half2float(qkv[(long)r*KQKV + 2*CDIM + c]) : 0.f;
  }
  #pragma unroll
  for (int t=0;t<8;t++){
    float acc = 0.f;
    #pragma unroll
    for (int u=0;u<33;u++) acc = fmaf(wl[u], vb[t+u], acc);
    att[(long)(i0+t)*CDIM + c] = acc;
  }
}

__global__ void build_wc_k(const float* __restrict__ w7, const float* __restrict__ w5,
                           const float* __restrict__ w3, float* __restrict__ wc){
  int c = blockIdx.x, k = threadIdx.x;
  int ky = k/7, kx = k%7, dy = ky-3, dx = kx-3;
  float w = w7[c*49 + k];
  if (dy>=-2 && dy<=2 && dx>=-2 && dx<=2) w += w5[c*25 + (dy+2)*5 + (dx+2)];
  if (dy>=-1 && dy<=1 && dx>=-1 && dx<=1) w += w3[c*9  + (dy+1)*3 + (dx+1)];
  if (dy==0 && dx==0) w += 1.f;
  wc[k*CDIM + c] = w;
}

__global__ void cls_copy_k(const float* __restrict__ hin, float* __restrict__ hout){
  hout[threadIdx.x] = hin[threadIdx.x];
  hout[256+threadIdx.x] = hin[256+threadIdx.x];
}

__global__ void ppeg_k(const float* __restrict__ hin, float* __restrict__ hout,
                       const float* __restrict__ wc,
                       const float* __restrict__ b7, const float* __restrict__ b5,
                       const float* __restrict__ b3){
  int bx = blockIdx.x;
  int c  = blockIdx.y*128 + threadIdx.x;
  int y  = bx / 25;
  int xg = (bx % 25) * 4;
  float bsum = b7[c] + b5[c] + b3[c];
  float acc[4] = {bsum, bsum, bsum, bsum};
  #pragma unroll
  for (int ky=0; ky<7; ky++){
    int yy = y + ky - 3;
    bool vy = (yy>=0 && yy<100);
    #pragma unroll
    for (int dx=-3; dx<=6; dx++){
      int xx = xg + dx;
      float v = (vy && xx>=0 && xx<100) ? hin[(long)(1 + yy*100 + xx)*CDIM + c] : 0.f;
      #pragma unroll
      for (int j=0;j<4;j++){
        int kx = dx - j + 3;
        if (kx>=0 && kx<7) acc[j] = fmaf(wc[(ky*7+kx)*CDIM + c], v, acc[j]);
      }
    }
  }
  #pragma unroll
  for (int j=0;j<4;j++)
    hout[(long)(1 + y*100 + xg + j)*CDIM + c] = acc[j];
}

__global__ void addres_k(float* __restrict__ h, const float* __restrict__ tmp,
                         const float* __restrict__ bias){
  long idx = (long)blockIdx.x*256 + threadIdx.x;
  if (idx >= SZ_H) return;
  int c = (int)(idx & (CDIM-1));
  h[idx] += tmp[idx] + bias[c];
}

static void run_attn_block(float* base, float* h,
                           const float* lng, const float* lnb,
                           const __half* qkvwR, const __half* outwR, const float* outb,
                           const float* resw,
                           cudaStream_t sB, cudaStream_t sC,
                           cudaEvent_t eF, cudaEvent_t eJ, cudaEvent_t eC)
{
  __half* lnxh = (__half*)(base + OFF_LNX);
  __half* qkvh = (__half*)(base + OFF_QKV);
  __half* qlh  = (__half*)(base + OFF_QL);
  __half* klh  = (__half*)(base + OFF_KL);
  __half* zAh  = (__half*)(base + OFF_ZAH);
  __half* atth = (__half*)(base + OFF_ATTH);
  __half* a3vh = (__half*)(base + OFF_A3V);
  float* a3   = base + OFF_A3;
  float* a2   = base + OFF_A2;
  float* zA   = base + OFF_ZA;
  float* zB   = base + OFF_ZB;
  float* xz   = base + OFF_XZ;
  float* tb   = base + OFF_TB;
  float* ub   = base + OFF_UB;
  float* cs   = base + OFF_CS;
  float* rs   = base + OFF_RS;
  float* sc   = base + OFF_SC;
  float* a3vp = base + OFF_A3VP;
  float* w2   = base + OFF_W2;
  float* att  = base + OFF_ATT;
  float* tmp  = base + OFF_TMP;
  float* m3   = base + OFF_M3;
  float* i3   = base + OFF_I3;
  int*   cnt  = (int*)(base + OFF_CNT);

  ln_h_k<<<NTOK,128>>>(h, lnxh + (long)PADN*CDIM, lng, lnb);

  // qkvh = lnxh @ W (half out)
  gemm16<128,false,true><<<dim3(KQKV/128, NP/128, 1), 256, DSM16_NN128>>>(
      lnxh, CDIM, 0, qkvwR, KQKV, 0, qkvh, KQKV, 0, NP, KQKV, CDIM, 1.f);

  landmarks_k<<<dim3(NL,NH), DH>>>(qkvh, qlh, klh);

  cudaEventRecord(eF, 0);
  cudaStreamWaitEvent(sB, eF, 0);
  cudaStreamWaitEvent(sC, eF, 0);

  conv_res_k<<<(NP/8)*CDIM/256, 256, 0, sC>>>(qkvh, resw, att);
  cudaEventRecord(eC, sC);

  gemm16<128,true,false><<<dim3(2, 2, NH), 256, DSM16_NT128, sB>>>(
      qlh, DH, (long)NL*DH, klh, DH, (long)NL*DH, a2, NL, (long)NL*NL, NL, NL, DH, 0.125f);
  softmax256<<<NH*NL, 256, 0, sB>>>(a2);
  colsum_k<<<8,256,0,sB>>>(a2, cs);
  rowsum_k<<<8,256,0,sB>>>(a2, rs);
  maxmul_k<<<1,256,0,sB>>>(cs, rs, sc);
  zero_k<<<1,256,0,sB>>>(base + OFF_CNT, 256);
  pinv_k<<<dim3(4,NH), 256, 0, sB>>>(a2, zA, zB, xz, ub, tb, sc, cnt);
  f2h_k<<<(unsigned)(SZ_A2/256),256,0,sB>>>(zA, zAh, SZ_A2);
  cudaEventRecord(eJ, sB);

  gemm16<128,true,false><<<dim3(NP/128, 2, NH), 256, DSM16_NT128>>>(
      qlh, DH, (long)NL*DH, qkvh + CDIM, KQKV, 64, a3, NP, (long)NL*NP, NL, NP, DH, 0.125f);
  rowstat3_k<<<dim3(NL,NH), 256>>>(a3, m3, i3);
  a3v_partial_k<<<dim3(32,NH),256>>>(a3, qkvh, m3, i3, a3vp);
  a3v_reduce_k<<<(unsigned)((NH*NL*DH)/256),256>>>(a3vp, a3vh);

  cudaStreamWaitEvent(0, eJ, 0);
  gemm16<64,false,false><<<dim3(1,2,NH), 256, DSM16_NN64>>>(
      zAh, NL, (long)NL*NL, a3vh, DH, (long)NL*DH, w2, DH, (long)NL*DH, NL, DH, NL, 1.f);

  cudaStreamWaitEvent(0, eC, 0);
  a1w2f_k<<<dim3(NP/128, NH), 256, DSM_A1W2F>>>(qkvh, klh, w2, att);

  f2h_k<<<(unsigned)(SZ_LNX/256),256>>>(att, atth, SZ_LNX);
  gemm16<128,false,false><<<dim3(CDIM/128, MPAD/128, 1), 256, DSM16_NN128>>>(
      atth + (long)PADN*CDIM, CDIM, 0, outwR, CDIM, 0, tmp, CDIM, 0, NTOK, CDIM, CDIM, 1.f);
  addres_k<<<(unsigned)((SZ_H+255)/256),256>>>(h, tmp, outb);
}

extern "C" void kernel_launch(void* const* d_in, const int* in_sizes, int n_in,
                              void* d_out, int out_size)
{
  (void)in_sizes; (void)n_in; (void)out_size;
  const float* features = (const float*)d_in[0];
  const float* cls      = (const float*)d_in[1];
  const float* ln1_g    = (const float*)d_in[2];
  const float* ln1_b    = (const float*)d_in[3];
  const float* qkv1_w   = (const float*)d_in[4];
  const float* out1_w   = (const float*)d_in[5];
  const float* out1_b   = (const float*)d_in[6];
  const float* res1_w   = (const float*)d_in[7];
  const float* w7       = (const float*)d_in[8];
  const float* b7       = (const float*)d_in[9];
  const float* w5       = (const float*)d_in[10];
  const float* b5       = (const float*)d_in[11];
  const float* w3       = (const float*)d_in[12];
  const float* b3       = (const float*)d_in[13];
  const float* ln2_g    = (const float*)d_in[14];
  const float* ln2_b    = (const float*)d_in[15];
  const float* qkv2_w   = (const float*)d_in[16];
  const float* out2_w   = (const float*)d_in[17];
  const float* out2_b   = (const float*)d_in[18];
  const float* res2_w   = (const float*)d_in[19];
  const float* lnf_g    = (const float*)d_in[20];
  const float* lnf_b    = (const float*)d_in[21];

  cudaFuncSetAttribute((const void*)a1w2f_k, cudaFuncAttributeMaxDynamicSharedMemorySize, DSM_A1W2F);

  float* base = nullptr;
  cudaGetSymbolAddress((void**)&base, g_scratch);

  static cudaStream_t sB = nullptr, sC = nullptr;
  static cudaEvent_t eF1, eJ1, eC1, eF2, eJ2, eC2;
  if (!sB){
    cudaStreamCreateWithFlags(&sB, cudaStreamNonBlocking);
    cudaStreamCreateWithFlags(&sC, cudaStreamNonBlocking);
    cudaEventCreateWithFlags(&eF1, cudaEventDisableTiming);
    cudaEventCreateWithFlags(&eJ1, cudaEventDisableTiming);
    cudaEventCreateWithFlags(&eC1, cudaEventDisableTiming);
    cudaEventCreateWithFlags(&eF2, cudaEventDisableTiming);
    cudaEventCreateWithFlags(&eJ2, cudaEventDisableTiming);
    cudaEventCreateWithFlags(&eC2, cudaEventDisableTiming);
  }

  float* hA = base + OFF_HA;
  float* hB = base + OFF_HB;

  roundh_copy_k<<<(unsigned)(((long)CDIM*KQKV+255)/256),256>>>(qkv1_w, (__half*)(base + OFF_W1R), (long)CDIM*KQKV);
  roundh_copy_k<<<(unsigned)(((long)CDIM*CDIM+255)/256),256>>>(out1_w, (__half*)(base + OFF_O1R), (long)CDIM*CDIM);
  roundh_copy_k<<<(unsigned)(((long)CDIM*KQKV+255)/256),256>>>(qkv2_w, (__half*)(base + OFF_W2R), (long)CDIM*KQKV);
  roundh_copy_k<<<(unsigned)(((long)CDIM*CDIM+255)/256),256>>>(out2_w, (__half*)(base + OFF_O2R), (long)CDIM*CDIM);

  init_h_k<<<(unsigned)((SZ_H + 255)/256), 256>>>(features, cls, hA);
  zero_k<<<(unsigned)(((long)PADN*CDIM/2 + 255)/256), 256>>>(base + OFF_LNX, (long)PADN*CDIM/2);

  run_attn_block(base, hA, ln1_g, ln1_b, (__half*)(base + OFF_W1R), (__half*)(base + OFF_O1R),
                 out1_b, res1_w, sB, sC, eF1, eJ1, eC1);

  build_wc_k<<<CDIM, 49>>>(w7, w5, w3, base + OFF_WC);
  cls_copy_k<<<1,256>>>(hA, hB);
  ppeg_k<<<dim3(2500, 4), 128>>>(hA, hB, base + OFF_WC, b7, b5, b3);

  run_attn_block(base, hB, ln2_g, ln2_b, (__half*)(base + OFF_W2R), (__half*)(base + OFF_O2R),
                 out2_b, res2_w, sB, sC, eF2, eJ2, eC2);

  ln_k<<<NTOK, 128>>>(hB, (float*)d_out, lnf_g, lnf_b);
}

// round 16
// speedup vs baseline: 1.3789x; 1.0896x over previous
#include <cuda_runtime.h>
#include <cuda_fp16.h>
#include <cstdint>
#include <mma.h>
using namespace nvcuda;

#define NTOK 10001
#define CDIM 512
#define NP   10240
#define PADN 239
#define NH   8
#define DH   64
#define NL   256
#define LW   40
#define KQKV (3*CDIM)
#define MPAD 10112

constexpr long SZ_H    = (long)NTOK*CDIM;
constexpr long SZ_LNX  = (long)NP*CDIM;
constexpr long SZ_QKV  = (long)NP*KQKV;
constexpr long SZ_LAND = (long)NH*NL*DH;
constexpr long SZ_A1   = (long)NH*NP*NL;
constexpr long SZ_A2   = (long)NH*NL*NL;

constexpr long OFF_HA   = 0;
constexpr long OFF_HB   = OFF_HA  + SZ_H;
constexpr long OFF_LNX  = OFF_HB  + SZ_H;
constexpr long OFF_QKV  = OFF_LNX + SZ_LNX;
constexpr long OFF_QL   = OFF_QKV + SZ_QKV;
constexpr long OFF_KL   = OFF_QL  + SZ_LAND;
constexpr long OFF_A1   = OFF_KL  + SZ_LAND;
constexpr long OFF_ZAH  = OFF_A1;
constexpr long OFF_ATTH = OFF_A1  + SZ_A2;
constexpr long OFF_A3   = OFF_A1  + SZ_A1;     // half[NH*NL*NP]
constexpr long OFF_A2   = OFF_A3  + SZ_A1;
constexpr long OFF_ZA   = OFF_A2  + SZ_A2;
constexpr long OFF_ZB   = OFF_ZA  + SZ_A2;
constexpr long OFF_XZ   = OFF_ZB  + SZ_A2;
constexpr long OFF_TB   = OFF_XZ  + SZ_A2;
constexpr long OFF_UB   = OFF_TB  + SZ_A2;
constexpr long OFF_CS   = OFF_UB  + SZ_A2;
constexpr long OFF_RS   = OFF_CS  + 2048;
constexpr long OFF_SC   = OFF_RS  + 2048;
constexpr long OFF_A3VP = OFF_SC  + 8;
constexpr long SZ_A3VP  = (long)NH*32*NL*DH;
constexpr long OFF_A3V  = OFF_A3VP + SZ_A3VP;
constexpr long OFF_W2   = OFF_A3V + SZ_LAND;
constexpr long OFF_ATT  = OFF_W2  + SZ_LAND;
constexpr long OFF_TMP  = OFF_ATT + SZ_LNX;
constexpr long OFF_WC   = OFF_TMP + (long)MPAD*CDIM;
constexpr long OFF_CNT  = OFF_WC + 512*49;
constexpr long OFF_W1R  = OFF_CNT + 256;
constexpr long OFF_O1R  = OFF_W1R + (long)CDIM*KQKV;
constexpr long OFF_W2R  = OFF_O1R + (long)CDIM*CDIM;
constexpr long OFF_O2R  = OFF_W2R + (long)CDIM*KQKV;
constexpr long OFF_M3   = OFF_O2R + (long)CDIM*CDIM;
constexpr long OFF_I3   = OFF_M3 + 2048;
constexpr long SCRATCH_SZ = OFF_I3 + 2048 + 64;

static __device__ float g_scratch[SCRATCH_SZ];

__device__ __forceinline__ float tf32r(float x){
  unsigned int u;
  asm("cvt.rna.tf32.f32 %0, %1;\n" : "=r"(u) : "f"(x));
  return __uint_as_float(u);
}

__device__ __forceinline__ float warpMax(float v){
  #pragma unroll
  for (int o=16;o;o>>=1) v = fmaxf(v, __shfl_xor_sync(0xffffffffu, v, o));
  return v;
}
__device__ __forceinline__ float warpSum(float v){
  #pragma unroll
  for (int o=16;o;o>>=1) v += __shfl_xor_sync(0xffffffffu, v, o);
  return v;
}

__device__ __forceinline__ void cp16g(void* dst, const void* src, bool ok){
  unsigned int d = (unsigned int)__cvta_generic_to_shared(dst);
  int b = ok ? 16 : 0;
  asm volatile("cp.async.cg.shared.global [%0], [%1], 16, %2;\n" :: "r"(d), "l"(src), "r"(b));
}

__global__ void roundh_copy_k(const float* __restrict__ in, __half* __restrict__ out, long n){
  long i = (long)blockIdx.x*256 + threadIdx.x;
  if (i < n) out[i] = __float2half_rn(in[i]);
}

__global__ void f2h_k(const float* __restrict__ in, __half* __restrict__ out, long n){
  long i = (long)blockIdx.x*256 + threadIdx.x;
  if (i < n) out[i] = __float2half_rn(in[i]);
}

__global__ void init_h_k(const float* __restrict__ feat, const float* __restrict__ cls,
                         float* __restrict__ h){
  long i = (long)blockIdx.x*256 + threadIdx.x;
  if (i >= SZ_H) return;
  h[i] = (i < CDIM) ? cls[i] : feat[i - CDIM];
}

__global__ void zero_k(float* __restrict__ p, long n){
  long i = (long)blockIdx.x*256 + threadIdx.x;
  if (i < n) p[i] = 0.f;
}

__global__ void ln_h_k(const float* __restrict__ x, __half* __restrict__ y,
                       const float* __restrict__ g, const float* __restrict__ b){
  const int t = blockIdx.x;
  const float* xr = x + (long)t*CDIM;
  __half* yr = y + (long)t*CDIM;
  int tid = threadIdx.x;
  float s = 0.f, s2 = 0.f;
  #pragma unroll
  for (int c = tid; c < CDIM; c += 128){ float v = xr[c]; s += v; s2 += v*v; }
  #pragma unroll
  for (int o=16;o;o>>=1){ s += __shfl_xor_sync(0xffffffffu,s,o); s2 += __shfl_xor_sync(0xffffffffu,s2,o); }
  __shared__ float sm[4], sm2[4];
  if ((tid&31)==0){ sm[tid>>5]=s; sm2[tid>>5]=s2; }
  __syncthreads();
  s  = sm[0]+sm[1]+sm[2]+sm[3];
  s2 = sm2[0]+sm2[1]+sm2[2]+sm2[3];
  float mu  = s * (1.f/CDIM);
  float var = s2 * (1.f/CDIM) - mu*mu;
  float inv = rsqrtf(var + 1e-5f);
  #pragma unroll
  for (int c = tid; c < CDIM; c += 128)
    yr[c] = __float2half_rn((xr[c]-mu)*inv*g[c] + b[c]);
}

__global__ void ln_k(const float* __restrict__ x, float* __restrict__ y,
                     const float* __restrict__ g, const float* __restrict__ b){
  const int t = blockIdx.x;
  const float* xr = x + (long)t*CDIM;
  float* yr = y + (long)t*CDIM;
  int tid = threadIdx.x;
  float s = 0.f, s2 = 0.f;
  #pragma unroll
  for (int c = tid; c < CDIM; c += 128){ float v = xr[c]; s += v; s2 += v*v; }
  #pragma unroll
  for (int o=16;o;o>>=1){ s += __shfl_xor_sync(0xffffffffu,s,o); s2 += __shfl_xor_sync(0xffffffffu,s2,o); }
  __shared__ float sm[4], sm2[4];
  if ((tid&31)==0){ sm[tid>>5]=s; sm2[tid>>5]=s2; }
  __syncthreads();
  s  = sm[0]+sm[1]+sm[2]+sm[3];
  s2 = sm2[0]+sm2[1]+sm2[2]+sm2[3];
  float mu  = s * (1.f/CDIM);
  float var = s2 * (1.f/CDIM) - mu*mu;
  float inv = rsqrtf(var + 1e-5f);
  #pragma unroll
  for (int c = tid; c < CDIM; c += 128)
    yr[c] = (xr[c]-mu)*inv*g[c] + b[c];
}

// ---------- fp16 tensor-core GEMM, fp32 accumulate, 2-stage cp.async ----------
template<int BN, bool NT, bool HOUT>
__global__ void __launch_bounds__(256,2) gemm16(
                        const __half* __restrict__ A, int lda, long sA,
                        const __half* __restrict__ B, int ldb, long sB,
                        void* __restrict__ Cv, int ldc, long sC,
                        int M, int N, int K, float alpha)
{
  constexpr int BM=128, BK=32, BKP=40, BNPH=BN+8;
  constexpr int WN = BN/2, NF = WN/16;
  constexpr int ASZ = BM*BKP;
  constexpr int BSZ = NT ? BN*BKP : BK*BNPH;
  extern __shared__ __half dynh[];
  __half* Asm = dynh;
  __half* Bsm = dynh + 2*ASZ;

  const int tid = threadIdx.x;
  const int wid = tid >> 5;
  const int warp_m = wid & 3, warp_n = wid >> 2;
  const int bm = blockIdx.y*BM, bn = blockIdx.x*BN;
  A += (long)blockIdx.z * sA;
  B += (long)blockIdx.z * sB;

  wmma::fragment<wmma::accumulator,16,16,16,float> acc[2][NF];
  #pragma unroll
  for (int im=0;im<2;im++)
    #pragma unroll
    for (int jn=0;jn<NF;jn++) wmma::fill_fragment(acc[im][jn], 0.f);

  auto loadA = [&](int s, int k0){
    __half* As = Asm + s*ASZ;
    #pragma unroll
    for (int i=0;i<2;i++){
      int lin = tid + i*256;
      int r = lin >> 2, k8 = (lin & 3)*8;
      int gr = bm + r;
      bool ok = gr < M;
      const __half* src = A + (long)(ok ? gr : bm)*lda + k0 + k8;
      cp16g(As + r*BKP + k8, src, ok);
    }
  };
  auto loadB = [&](int s, int k0){
    __half* Bs = Bsm + s*BSZ;
    if (!NT){
      constexpr int NCH = (BK*BN/8)/256;
      #pragma unroll
      for (int i=0;i<NCH;i++){
        int lin = tid + i*256;
        int kk = lin / (BN/8), c8 = (lin % (BN/8))*8;
        cp16g(Bs + kk*BNPH + c8, B + (long)(k0+kk)*ldb + bn + c8, true);
      }
    } else {
      constexpr int NCH = (BN*BK/8)/256;
      #pragma unroll
      for (int i=0;i<NCH;i++){
        int lin = tid + i*256;
        int c = lin >> 2, k8 = (lin & 3)*8;
        cp16g(Bs + c*BKP + k8, B + (long)(bn+c)*ldb + k0 + k8, true);
      }
    }
  };

  const int nt = K/BK;
  loadA(0, 0); loadB(0, 0);
  asm volatile("cp.async.commit_group;\n");
  for (int t=0; t<nt; t++){
    int cs = t & 1;
    if (t+1 < nt){
      loadA((t+1)&1, (t+1)*BK);
      loadB((t+1)&1, (t+1)*BK);
      asm volatile("cp.async.commit_group;\n");
      asm volatile("cp.async.wait_group 1;\n");
    } else {
      asm volatile("cp.async.wait_group 0;\n");
    }
    __syncthreads();
    __half* As = Asm + cs*ASZ;
    __half* Bs = Bsm + cs*BSZ;
    #pragma unroll
    for (int kk=0; kk<BK; kk+=16){
      wmma::fragment<wmma::matrix_a,16,16,16,__half,wmma::row_major> af[2];
      #pragma unroll
      for (int im=0;im<2;im++)
        wmma::load_matrix_sync(af[im], As + (warp_m*32 + im*16)*BKP + kk, BKP);
      if (!NT){
        wmma::fragment<wmma::matrix_b,16,16,16,__half,wmma::row_major> bf[NF];
        #pragma unroll
        for (int jn=0;jn<NF;jn++)
          wmma::load_matrix_sync(bf[jn], Bs + kk*BNPH + warp_n*WN + jn*16, BNPH);
        #pragma unroll
        for (int im=0;im<2;im++)
          #pragma unroll
          for (int jn=0;jn<NF;jn++)
            wmma::mma_sync(acc[im][jn], af[im], bf[jn], acc[im][jn]);
      } else {
        wmma::fragment<wmma::matrix_b,16,16,16,__half,wmma::col_major> bf[NF];
        #pragma unroll
        for (int jn=0;jn<NF;jn++)
          wmma::load_matrix_sync(bf[jn], Bs + (warp_n*WN + jn*16)*BKP + kk, BKP);
        #pragma unroll
        for (int im=0;im<2;im++)
          #pragma unroll
          for (int jn=0;jn<NF;jn++)
            wmma::mma_sync(acc[im][jn], af[im], bf[jn], acc[im][jn]);
      }
    }
    __syncthreads();
  }
  #pragma unroll
  for (int im=0;im<2;im++)
    #pragma unroll
    for (int jn=0;jn<NF;jn++)
      #pragma unroll
      for (int e=0;e<acc[im][jn].num_elements;e++)
        acc[im][jn].x[e] *= alpha;

  if (!HOUT){
    float* C = (float*)Cv + (long)blockIdx.z * sC;
    #pragma unroll
    for (int im=0;im<2;im++)
      #pragma unroll
      for (int jn=0;jn<NF;jn++){
        int gr = bm + warp_m*32 + im*16;
        if (gr < M)
          wmma::store_matrix_sync(C + (long)gr*ldc + bn + warp_n*WN + jn*16,
                                  acc[im][jn], ldc, wmma::mem_row_major);
      }
  } else {
    __half* C = (__half*)Cv + (long)blockIdx.z * sC;
    float* stg = (float*)dynh;
    constexpr int BNP4 = BN+4;
    __syncthreads();
    #pragma unroll
    for (int phase=0; phase<2; phase++){
      if ((warp_m >> 1) == phase){
        int rloc = (warp_m & 1)*32;
        #pragma unroll
        for (int im=0;im<2;im++)
          #pragma unroll
          for (int jn=0;jn<NF;jn++)
            wmma::store_matrix_sync(stg + (rloc + im*16)*BNP4 + warp_n*WN + jn*16,
                                    acc[im][jn], BNP4, wmma::mem_row_major);
      }
      __syncthreads();
      constexpr int NCH = (64*BN/8)/256;
      #pragma unroll
      for (int i=0;i<NCH;i++){
        int lin = tid + i*256;
        int r = lin / (BN/8), c8 = (lin % (BN/8))*8;
        int gr = bm + phase*64 + r;
        if (gr < M){
          const float* sp = stg + r*BNP4 + c8;
          __half2 h0 = __floats2half2_rn(sp[0], sp[1]);
          __half2 h1 = __floats2half2_rn(sp[2], sp[3]);
          __half2 h2 = __floats2half2_rn(sp[4], sp[5]);
          __half2 h3 = __floats2half2_rn(sp[6], sp[7]);
          __half2* dp = (__half2*)(C + (long)gr*ldc + bn + c8);
          dp[0]=h0; dp[1]=h1; dp[2]=h2; dp[3]=h3;
        }
      }
      __syncthreads();
    }
  }
}

constexpr int DSM16_NN128 = (2*(128*40) + 2*(32*136))*2;
constexpr int DSM16_NT128 = (2*(128*40) + 2*(128*40))*2;
constexpr int DSM16_NN64  = (2*(128*40) + 2*(32*72))*2;

__global__ void landmarks_k(const __half* __restrict__ qkv,
                            __half* __restrict__ ql, __half* __restrict__ kl){
  int j = blockIdx.x, h = blockIdx.y, d = threadIdx.x;
  const __half* base = qkv + (long)(j*LW)*KQKV + h*DH + d;
  float sq = 0.f, sk = 0.f;
  #pragma unroll 8
  for (int t=0;t<LW;t++){
    sq += __half2float(base[(long)t*KQKV]);
    sk += __half2float(base[(long)t*KQKV + CDIM]);
  }
  long o = ((long)h*NL + j)*DH + d;
  ql[o] = __float2half_rn(sq * (1.f/LW));
  kl[o] = __float2half_rn(sk * (1.f/LW));
}

__global__ void softmax256(float* __restrict__ x){
  float* p = x + (long)blockIdx.x * NL;
  int tid = threadIdx.x;
  float v = p[tid];
  __shared__ float sm[8];
  float m = warpMax(v);
  if ((tid&31)==0) sm[tid>>5]=m;
  __syncthreads();
  if (tid < 32){ float t = (tid<8)? sm[tid] : -3.4e38f; t = warpMax(t); if (tid==0) sm[0]=t; }
  __syncthreads();
  m = sm[0];
  __syncthreads();
  float e = __expf(v - m);
  float s = warpSum(e);
  if ((tid&31)==0) sm[tid>>5]=s;
  __syncthreads();
  if (tid < 32){ float t = (tid<8)? sm[tid] : 0.f; t = warpSum(t); if (tid==0) sm[0]=t; }
  __syncthreads();
  p[tid] = tf32r(e / sm[0]);
}

// per-row max + invsum of raw sim3 (half)
__global__ void rowstat3_k(const __half* __restrict__ a3, float* __restrict__ m3,
                           float* __restrict__ i3){
  int r = blockIdx.x, h = blockIdx.y, tid = threadIdx.x;
  const __half* p = a3 + ((long)h*NL + r)*NP;
  float va[NP/256];
  float m = -3.4e38f;
  #pragma unroll
  for (int i=0;i<NP/256;i++){ va[i] = __half2float(p[tid + i*256]); m = fmaxf(m, va[i]); }
  __shared__ float sm[8];
  m = warpMax(m);
  if ((tid&31)==0) sm[tid>>5]=m;
  __syncthreads();
  if (tid < 32){ float t = (tid<8)? sm[tid] : -3.4e38f; t = warpMax(t); if (tid==0) sm[0]=t; }
  __syncthreads();
  m = sm[0];
  __syncthreads();
  float s = 0.f;
  #pragma unroll
  for (int i=0;i<NP/256;i++) s += __expf(va[i]-m);
  s = warpSum(s);
  if ((tid&31)==0) sm[tid>>5]=s;
  __syncthreads();
  if (tid < 32){ float t = (tid<8)? sm[tid] : 0.f; t = warpSum(t); if (tid==0) sm[0]=t; }
  __syncthreads();
  if (tid==0){ m3[h*NL+r]=m; i3[h*NL+r]=1.f/sm[0]; }
}

__global__ void colsum_k(const float* __restrict__ a2, float* __restrict__ cs){
  int row = blockIdx.x*256 + threadIdx.x;
  const float* p = a2 + (long)row*NL;
  float s = 0.f;
  for (int j=0;j<NL;j++) s += fabsf(p[j]);
  cs[row] = s;
}
__global__ void rowsum_k(const float* __restrict__ a2, float* __restrict__ rs){
  int h = blockIdx.x, j = threadIdx.x;
  float s = 0.f;
  for (int i=0;i<NL;i++) s += fabsf(a2[((long)h*NL + i)*NL + j]);
  rs[h*NL + j] = s;
}
__global__ void maxmul_k(const float* __restrict__ cs, const float* __restrict__ rs,
                         float* __restrict__ sc){
  int tid = threadIdx.x;
  float mc = -3.4e38f, mr = -3.4e38f;
  for (int i = tid; i < NH*NL; i += 256){ mc = fmaxf(mc, cs[i]); mr = fmaxf(mr, rs[i]); }
  __shared__ float sa[8], sb[8];
  mc = warpMax(mc); mr = warpMax(mr);
  if ((tid&31)==0){ sa[tid>>5]=mc; sb[tid>>5]=mr; }
  __syncthreads();
  if (tid < 32){
    float a = (tid<8)? sa[tid] : -3.4e38f;
    float b = (tid<8)? sb[tid] : -3.4e38f;
    a = warpMax(a); b = warpMax(b);
    if (tid==0) sc[0] = a*b;
  }
}

// ---------- persistent pinv (tf32, unchanged) ----------
struct PinvSmem { float As[64][40]; float Bs[32][264]; };

__device__ __forceinline__ void head_bar(int* c, int tid){
  __syncthreads();
  if (tid == 0){
    __threadfence();
    atomicAdd(c, 1);
    while (atomicAdd(c, 0) < 4) __nanosleep(32);
    __threadfence();
  }
  __syncthreads();
}

__device__ void pinv_mm(const float* __restrict__ L, const float* __restrict__ R,
                        float* __restrict__ O, int rb, float beta, float alphaD, bool tr,
                        PinvSmem* s)
{
  int tid = threadIdx.x, wid = tid>>5;
  int wm = wid & 1, wn = wid >> 1;
  wmma::fragment<wmma::accumulator,16,16,8,float> acc[2][4];
  #pragma unroll
  for (int im=0;im<2;im++)
    #pragma unroll
    for (int jn=0;jn<4;jn++) wmma::fill_fragment(acc[im][jn], 0.f);

  for (int k0=0; k0<NL; k0+=32){
    #pragma unroll
    for (int i=0;i<2;i++){
      int lin = tid + i*256;
      int r = lin >> 3, k4 = (lin & 7)*4;
      float4 v = __ldcg((const float4*)&L[(long)(rb*64+r)*NL + k0 + k4]);
      *(float4*)&s->As[r][k4] = v;
    }
    #pragma unroll
    for (int i=0;i<8;i++){
      int lin = tid + i*256;
      int kk = lin >> 6, c4 = (lin & 63)*4;
      float4 v = __ldcg((const float4*)&R[(long)(k0+kk)*NL + c4]);
      if (tr){
        int gk = k0 + kk;
        v.x = tf32r(beta*v.x + ((gk==c4  ) ? alphaD : 0.f));
        v.y = tf32r(beta*v.y + ((gk==c4+1) ? alphaD : 0.f));
        v.z = tf32r(beta*v.z + ((gk==c4+2) ? alphaD : 0.f));
        v.w = tf32r(beta*v.w + ((gk==c4+3) ? alphaD : 0.f));
      }
      *(float4*)&s->Bs[kk][c4] = v;
    }
    __syncthreads();
    #pragma unroll
    for (int kk=0; kk<32; kk+=8){
      wmma::fragment<wmma::matrix_a,16,16,8,wmma::precision::tf32,wmma::row_major> af[2];
      wmma::fragment<wmma::matrix_b,16,16,8,wmma::precision::tf32,wmma::row_major> bf[4];
      #pragma unroll
      for (int im=0;im<2;im++)
        wmma::load_matrix_sync(af[im], &s->As[wm*32 + im*16][kk], 40);
      #pragma unroll
      for (int jn=0;jn<4;jn++)
        wmma::load_matrix_sync(bf[jn], &s->Bs[kk][wn*64 + jn*16], 264);
      #pragma unroll
      for (int im=0;im<2;im++)
        #pragma unroll
        for (int jn=0;jn<4;jn++)
          wmma::mma_sync(acc[im][jn], af[im], bf[jn], acc[im][jn]);
    }
    __syncthreads();
  }
  #pragma unroll
  for (int im=0;im<2;im++)
    #pragma unroll
    for (int jn=0;jn<4;jn++){
      #pragma unroll
      for (int e=0;e<acc[im][jn].num_elements;e++)
        acc[im][jn].x[e] = tf32r(acc[im][jn].x[e]);
      wmma::store_matrix_sync(&O[(long)(rb*64 + wm*32 + im*16)*NL + wn*64 + jn*16],
                              acc[im][jn], NL, wmma::mem_row_major);
    }
}

__global__ void pinv_k(const float* __restrict__ a2f, float* __restrict__ zAf,
                       float* __restrict__ zBf, float* __restrict__ xzf,
                       float* __restrict__ ubf, float* __restrict__ tbf,
                       const float* __restrict__ sc, int* __restrict__ cnt)
{
  __shared__ PinvSmem s;
  int rb = blockIdx.x, h = blockIdx.y, tid = threadIdx.x;
  const long HS = (long)h*NL*NL;
  const float* a2 = a2f + HS;
  float* ZA = zAf + HS; float* ZB = zBf + HS;
  float* XZ = xzf + HS; float* UB = ubf + HS; float* TB = tbf + HS;
  int* c = cnt + h*32;

  float inv = 1.f / sc[0];
  for (int idx = tid; idx < 64*NL; idx += 256){
    int i = rb*64 + (idx >> 8), j = idx & 255;
    ZA[(long)i*NL + j] = tf32r(__ldcg(&a2[(long)j*NL + i]) * inv);
  }
  int step = 0;
  head_bar(c + step++, tid);

  float* cur = ZA; float* nxt = ZB;
  for (int it=0; it<6; ++it){
    pinv_mm(a2, cur, XZ, rb, 0.f, 0.f, false, &s);        head_bar(c + step++, tid);
    pinv_mm(XZ, XZ, UB, rb, -1.f, 7.f, true, &s);         head_bar(c + step++, tid);
    pinv_mm(XZ, UB, TB, rb, -1.f, 15.f, true, &s);        head_bar(c + step++, tid);
    pinv_mm(cur, TB, nxt, rb, -0.25f, 3.25f, true, &s);   head_bar(c + step++, tid);
    float* t = cur; cur = nxt; nxt = t;
  }
}

// a3v with softmax folded in; a3 and v half
__global__ void a3v_partial_k(const __half* __restrict__ a3, const __half* __restrict__ qkv,
                              const float* __restrict__ m3, const float* __restrict__ i3,
                              float* __restrict__ part){
  int ch = blockIdx.x, h = blockIdx.y;
  int tid = threadIdx.x;
  __shared__ float a3s[256][33];
  __shared__ float vs[32][DH];
  __shared__ float m3s[256], i3s[256];
  m3s[tid] = m3[h*NL + tid];
  i3s[tid] = i3[h*NL + tid];
  __syncthreads();
  float acc[DH];
  #pragma unroll
  for (int d=0;d<DH;d++) acc[d]=0.f;
  int k0base = ch * (NP/32);
  for (int kk0 = 0; kk0 < NP/32; kk0 += 32) {
    int kbase = k0base + kk0;
    #pragma unroll
    for (int idx = tid; idx < 256*32; idx += 256) {
      int r = idx >> 5, k = idx & 31;
      float raw = __half2float(a3[((long)h*NL + r)*NP + kbase + k]);
      a3s[r][k] = __expf(raw - m3s[r]) * i3s[r];
    }
    #pragma unroll
    for (int idx = tid; idx < 32*DH; idx += 256) {
      int k = idx >> 6, d = idx & 63;
      vs[k][d] = __half2float(qkv[(long)(kbase+k)*KQKV + 2*CDIM + h*DH + d]);
    }
    __syncthreads();
    #pragma unroll 4
    for (int k=0;k<32;k++){
      float pp = a3s[tid][k];
      #pragma unroll
      for (int d=0;d<DH;d++) acc[d] = fmaf(pp, vs[k][d], acc[d]);
    }
    __syncthreads();
  }
  float* o = part + (((long)h*32 + ch)*NL + tid)*DH;
  #pragma unroll
  for (int d=0;d<DH;d++) o[d] = acc[d];
}
__global__ void a3v_reduce_k(const float* __restrict__ part, __half* __restrict__ out){
  int idx = blockIdx.x*256 + threadIdx.x;
  int h = idx >> 14;
  int rem = idx & 16383;
  float s = 0.f;
  #pragma unroll
  for (int ch=0; ch<32; ch++)
    s += part[(((long)h*32 + ch) << 14) + rem];
  out[idx] = __float2half_rn(s);
}

// ---- fused fp16: S = q@kl^T ; softmax(0.125*S) ; att += Sh @ Wh ----
#define SLD 260
#define SLDH 264
__global__ void __launch_bounds__(256,1) a1w2f_k(const __half* __restrict__ qkv,
                                                 const __half* __restrict__ kl,
                                                 const float* __restrict__ w2,
                                                 float* __restrict__ att){
  extern __shared__ float sm_[];
  float*  S   = sm_;                         // [128][SLD] fp32; later reused as Sh [128][SLDH] half
  __half* QH  = (__half*)(sm_ + 128*SLD);    // [128][72]
  __half* KLH = QH + 128*72;                 // [128][72]
  __half* WH  = QH;                          // [256][72] overlays QH..KLH (phase 3)
  __half* Sh  = (__half*)sm_;
  int tid = threadIdx.x;
  int h = blockIdx.y;
  long rowbase = (long)blockIdx.x*128;
  int wid = tid>>5;

  // load Q tile [128][64] half
  #pragma unroll
  for (int i=0;i<4;i++){
    int lin = tid + i*256;
    int r = lin >> 3, c8 = (lin & 7)*8;
    *(uint4*)&QH[r*72 + c8] = *(const uint4*)&qkv[(rowbase + r)*KQKV + h*DH + c8];
  }

  // phase 1: S = Q @ kl^T (fp16 MMA), two 128-landmark halves
  {
    int wm = wid & 3, wn = wid >> 2;
    for (int half_=0; half_<2; half_++){
      #pragma unroll
      for (int i=0;i<4;i++){
        int lin = tid + i*256;
        int r = lin >> 3, c8 = (lin & 7)*8;
        *(uint4*)&KLH[r*72 + c8] = *(const uint4*)&kl[((long)h*NL + half_*128 + r)*DH + c8];
      }
      __syncthreads();
      wmma::fragment<wmma::accumulator,16,16,16,float> acc[2][4];
      #pragma unroll
      for (int im=0;im<2;im++)
        #pragma unroll
        for (int jn=0;jn<4;jn++) wmma::fill_fragment(acc[im][jn], 0.f);
      #pragma unroll
      for (int k0=0;k0<DH;k0+=16){
        wmma::fragment<wmma::matrix_a,16,16,16,__half,wmma::row_major> af[2];
        wmma::fragment<wmma::matrix_b,16,16,16,__half,wmma::col_major> bf[4];
        #pragma unroll
        for (int im=0;im<2;im++)
          wmma::load_matrix_sync(af[im], QH + (wm*32 + im*16)*72 + k0, 72);
        #pragma unroll
        for (int jn=0;jn<4;jn++)
          wmma::load_matrix_sync(bf[jn], KLH + (wn*64 + jn*16)*72 + k0, 72);
        #pragma unroll
        for (int im=0;im<2;im++)
          #pragma unroll
          for (int jn=0;jn<4;jn++)
            wmma::mma_sync(acc[im][jn], af[im], bf[jn], acc[im][jn]);
      }
      #pragma unroll
      for (int im=0;im<2;im++)
        #pragma unroll
        for (int jn=0;jn<4;jn++)
          wmma::store_matrix_sync(S + (long)(wm*32 + im*16)*SLD + half_*128 + wn*64 + jn*16,
                                  acc[im][jn], SLD, wmma::mem_row_major);
      __syncthreads();
    }
  }

  // phase 2a: load W half (overlays QH/KLH)
  #pragma unroll
  for (int i=0;i<8;i++){
    int lin = tid + i*256;
    int r = lin >> 3, c8 = (lin & 7)*8;
    const float* sp = &w2[(long)h*NL*DH + r*DH + c8];
    __half2* dp = (__half2*)&WH[r*72 + c8];
    dp[0] = __floats2half2_rn(sp[0], sp[1]);
    dp[1] = __floats2half2_rn(sp[2], sp[3]);
    dp[2] = __floats2half2_rn(sp[4], sp[5]);
    dp[3] = __floats2half2_rn(sp[6], sp[7]);
  }
  // phase 2b: softmax rows of S (fp32)
  {
    int r = tid >> 1, hf = tid & 1;
    float* Sr = S + r*SLD + hf*128;
    float m = -3.4e38f;
    #pragma unroll
    for (int j=0;j<128;j++) m = fmaxf(m, Sr[j]);
    m = fmaxf(m, __shfl_xor_sync(0xffffffffu, m, 1));
    float s = 0.f;
    #pragma unroll
    for (int j=0;j<128;j++){ float e = __expf(0.125f*(Sr[j]-m)); Sr[j]=e; s += e; }
    s += __shfl_xor_sync(0xffffffffu, s, 1);
    float inv = 1.f/s;
    #pragma unroll
    for (int j=0;j<128;j++) Sr[j] = Sr[j]*inv;
  }
  __syncthreads();
  // phase 2c: in-place fp32->fp16 compaction (chunked read-all/sync/write-all)
  {
    #pragma unroll
    for (int c=0; c<32768; c+=1024){
      int e = c + tid*4;
      int r = e >> 8, j = e & 255;
      float4 v = *(float4*)&S[(long)r*SLD + j];
      __syncthreads();
      __half2* d = (__half2*)(Sh + (long)r*SLDH + j);
      d[0] = __floats2half2_rn(v.x, v.y);
      d[1] = __floats2half2_rn(v.z, v.w);
      __syncthreads();
    }
  }

  // phase 3: att_tile += Sh @ WH (fp16 MMA)
  {
    int wm = wid & 3, wn = wid >> 2;
    wmma::fragment<wmma::accumulator,16,16,16,float> acc[2][2];
    #pragma unroll
    for (int im=0;im<2;im++)
      #pragma unroll
      for (int jn=0;jn<2;jn++)
        wmma::load_matrix_sync(acc[im][jn],
            att + (rowbase + wm*32 + im*16)*CDIM + h*DH + wn*32 + jn*16,
            CDIM, wmma::mem_row_major);
    #pragma unroll
    for (int k0=0;k0<NL;k0+=16){
      wmma::fragment<wmma::matrix_a,16,16,16,__half,wmma::row_major> af[2];
      wmma::fragment<wmma::matrix_b,16,16,16,__half,wmma::row_major> bf[2];
      #pragma unroll
      for (int im=0;im<2;im++)
        wmma::load_matrix_sync(af[im], Sh + (long)(wm*32 + im*16)*SLDH + k0, SLDH);
      #pragma unroll
      for (int jn=0;jn<2;jn++)
        wmma::load_matrix_sync(bf[jn], WH + k0*72 + wn*32 + jn*16, 72);
      #pragma unroll
      for (int im=0;im<2;im++)
        #pragma unroll
        for (int jn=0;jn<2;jn++)
          wmma::mma_sync(acc[im][jn], af[im], bf[jn], acc[im][jn]);
    }
    #pragma unroll
    for (int im=0;im<2;im++)
      #pragma unroll
      for (int jn=0;jn<2;jn++)
        wmma::store_matrix_sync(att + (rowbase + wm*32 + im*16)*CDIM + h*DH + wn*32 + jn*16,
                                acc[im][jn], CDIM, wmma::mem_row_major);
  }
}
constexpr int DSM_A1W2F = 128*SLD*4 + 256*72*2;

// conv initializes att (fp32), v read as half
__global__ void conv_res_k(const __half* __restrict__ qkv, const float* __restrict__ rw,
                           float* __restrict__ att){
  int idx = blockIdx.x*256 + threadIdx.x;
  int c  = idx & (CDIM-1);
  int ig = idx >> 9;
  int i0 = ig*8;
  const float* w = rw + (c>>6)*33;
  float wl[33];
  #pragma unroll
  for (int u=0;u<33;u++) wl[u] = w[u];
  float vb[40];
  #pragma unroll
  for (int u=0;u<40;u++){
    int r = i0 - 16 + u;
    vb[u] = (r>=0 && r<NP) ? __half2float(qkv[(long)r*KQKV + 2*CDIM + c]) : 0.f;
  }
  #pragma unroll
  for (int t=0;t<8;t++){
    float acc = 0.f;
    #pragma unroll
    for (int u=0;u<33;u++) acc = fmaf(wl[u], vb[t+u], acc);
    att[(long)(i0+t)*CDIM + c] = acc;
  }
}

__global__ void build_wc_k(const float* __restrict__ w7, const float* __restrict__ w5,
                           const float* __restrict__ w3, float* __restrict__ wc){
  int c = blockIdx.x, k = threadIdx.x;
  int ky = k/7, kx = k%7, dy = ky-3, dx = kx-3;
  float w = w7[c*49 + k];
  if (dy>=-2 && dy<=2 && dx>=-2 && dx<=2) w += w5[c*25 + (dy+2)*5 + (dx+2)];
  if (dy>=-1 && dy<=1 && dx>=-1 && dx<=1) w += w3[c*9  + (dy+1)*3 + (dx+1)];
  if (dy==0 && dx==0) w += 1.f;
  wc[k*CDIM + c] = w;
}

__global__ void cls_copy_k(const float* __restrict__ hin, float* __restrict__ hout){
  hout[threadIdx.x] = hin[threadIdx.x];
  hout[256+threadIdx.x] = hin[256+threadIdx.x];
}

__global__ void ppeg_k(const float* __restrict__ hin, float* __restrict__ hout,
                       const float* __restrict__ wc,
                       const float* __restrict__ b7, const float* __restrict__ b5,
                       const float* __restrict__ b3){
  int bx = blockIdx.x;
  int c  = blockIdx.y*128 + threadIdx.x;
  int y  = bx / 25;
  int xg = (bx % 25) * 4;
  float bsum = b7[c] + b5[c] + b3[c];
  float acc[4] = {bsum, bsum, bsum, bsum};
  #pragma unroll
  for (int ky=0; ky<7; ky++){
    int yy = y + ky - 3;
    bool vy = (yy>=0 && yy<100);
    #pragma unroll
    for (int dx=-3; dx<=6; dx++){
      int xx = xg + dx;
      float v = (vy && xx>=0 && xx<100) ? hin[(long)(1 + yy*100 + xx)*CDIM + c] : 0.f;
      #pragma unroll
      for (int j=0;j<4;j++){
        int kx = dx - j + 3;
        if (kx>=0 && kx<7) acc[j] = fmaf(wc[(ky*7+kx)*CDIM + c], v, acc[j]);
      }
    }
  }
  #pragma unroll
  for (int j=0;j<4;j++)
    hout[(long)(1 + y*100 + xg + j)*CDIM + c] = acc[j];
}

__global__ void addres_k(float* __restrict__ h, const float* __restrict__ tmp,
                         const float* __restrict__ bias){
  long idx = (long)blockIdx.x*256 + threadIdx.x;
  if (idx >= SZ_H) return;
  int c = (int)(idx & (CDIM-1));
  h[idx] += tmp[idx] + bias[c];
}

static void run_attn_block(float* base, float* h,
                           const float* lng, const float* lnb,
                           const __half* qkvwR, const __half* outwR, const float* outb,
                           const float* resw,
                           cudaStream_t sB, cudaStream_t sC,
                           cudaEvent_t eF, cudaEvent_t eJ, cudaEvent_t eC)
{
  __half* lnxh = (__half*)(base + OFF_LNX);
  __half* qkvh = (__half*)(base + OFF_QKV);
  __half* qlh  = (__half*)(base + OFF_QL);
  __half* klh  = (__half*)(base + OFF_KL);
  __half* zAh  = (__half*)(base + OFF_ZAH);
  __half* atth = (__half*)(base + OFF_ATTH);
  __half* a3vh = (__half*)(base + OFF_A3V);
  __half* a3h  = (__half*)(base + OFF_A3);
  float* a2   = base + OFF_A2;
  float* zA   = base + OFF_ZA;
  float* zB   = base + OFF_ZB;
  float* xz   = base + OFF_XZ;
  float* tb   = base + OFF_TB;
  float* ub   = base + OFF_UB;
  float* cs   = base + OFF_CS;
  float* rs   = base + OFF_RS;
  float* sc   = base + OFF_SC;
  float* a3vp = base + OFF_A3VP;
  float* w2   = base + OFF_W2;
  float* att  = base + OFF_ATT;
  float* tmp  = base + OFF_TMP;
  float* m3   = base + OFF_M3;
  float* i3   = base + OFF_I3;
  int*   cnt  = (int*)(base + OFF_CNT);

  ln_h_k<<<NTOK,128>>>(h, lnxh + (long)PADN*CDIM, lng, lnb);

  gemm16<128,false,true><<<dim3(KQKV/128, NP/128, 1), 256, DSM16_NN128>>>(
      lnxh, CDIM, 0, qkvwR, KQKV, 0, qkvh, KQKV, 0, NP, KQKV, CDIM, 1.f);

  landmarks_k<<<dim3(NL,NH), DH>>>(qkvh, qlh, klh);

  cudaEventRecord(eF, 0);
  cudaStreamWaitEvent(sB, eF, 0);
  cudaStreamWaitEvent(sC, eF, 0);

  conv_res_k<<<(NP/8)*CDIM/256, 256, 0, sC>>>(qkvh, resw, att);
  cudaEventRecord(eC, sC);

  gemm16<128,true,false><<<dim3(2, 2, NH), 256, DSM16_NT128, sB>>>(
      qlh, DH, (long)NL*DH, klh, DH, (long)NL*DH, a2, NL, (long)NL*NL, NL, NL, DH, 0.125f);
  softmax256<<<NH*NL, 256, 0, sB>>>(a2);
  colsum_k<<<8,256,0,sB>>>(a2, cs);
  rowsum_k<<<8,256,0,sB>>>(a2, rs);
  maxmul_k<<<1,256,0,sB>>>(cs, rs, sc);
  zero_k<<<1,256,0,sB>>>(base + OFF_CNT, 256);
  pinv_k<<<dim3(4,NH), 256, 0, sB>>>(a2, zA, zB, xz, ub, tb, sc, cnt);
  f2h_k<<<(unsigned)(SZ_A2/256),256,0,sB>>>(zA, zAh, SZ_A2);
  cudaEventRecord(eJ, sB);

  // sim3 -> half a3
  gemm16<128,true,true><<<dim3(NP/128, 2, NH), 256, DSM16_NT128>>>(
      qlh, DH, (long)NL*DH, qkvh + CDIM, KQKV, 64, a3h, NP, (long)NL*NP, NL, NP, DH, 0.125f);
  rowstat3_k<<<dim3(NL,NH), 256>>>(a3h, m3, i3);
  a3v_partial_k<<<dim3(32,NH),256>>>(a3h, qkvh, m3, i3, a3vp);
  a3v_reduce_k<<<(unsigned)((NH*NL*DH)/256),256>>>(a3vp, a3vh);

  cudaStreamWaitEvent(0, eJ, 0);
  gemm16<64,false,false><<<dim3(1,2,NH), 256, DSM16_NN64>>>(
      zAh, NL, (long)NL*NL, a3vh, DH, (long)NL*DH, w2, DH, (long)NL*DH, NL, DH, NL, 1.f);

  cudaStreamWaitEvent(0, eC, 0);
  a1w2f_k<<<dim3(NP/128, NH), 256, DSM_A1W2F>>>(qkvh, klh, w2, att);

  f2h_k<<<(unsigned)(SZ_LNX/256),256>>>(att, atth, SZ_LNX);
  gemm16<128,false,false><<<dim3(CDIM/128, MPAD/128, 1), 256, DSM16_NN128>>>(
      atth + (long)PADN*CDIM, CDIM, 0, outwR, CDIM, 0, tmp, CDIM, 0, NTOK, CDIM, CDIM, 1.f);
  addres_k<<<(unsigned)((SZ_H+255)/256),256>>>(h, tmp, outb);
}

extern "C" void kernel_launch(void* const* d_in, const int* in_sizes, int n_in,
                              void* d_out, int out_size)
{
  (void)in_sizes; (void)n_in; (void)out_size;
  const float* features = (const float*)d_in[0];
  const float* cls      = (const float*)d_in[1];
  const float* ln1_g    = (const float*)d_in[2];
  const float* ln1_b    = (const float*)d_in[3];
  const float* qkv1_w   = (const float*)d_in[4];
  const float* out1_w   = (const float*)d_in[5];
  const float* out1_b   = (const float*)d_in[6];
  const float* res1_w   = (const float*)d_in[7];
  const float* w7       = (const float*)d_in[8];
  const float* b7       = (const float*)d_in[9];
  const float* w5       = (const float*)d_in[10];
  const float* b5       = (const float*)d_in[11];
  const float* w3       = (const float*)d_in[12];
  const float* b3       = (const float*)d_in[13];
  const float* ln2_g    = (const float*)d_in[14];
  const float* ln2_b    = (const float*)d_in[15];
  const float* qkv2_w   = (const float*)d_in[16];
  const float* out2_w   = (const float*)d_in[17];
  const float* out2_b   = (const float*)d_in[18];
  const float* res2_w   = (const float*)d_in[19];
  const float* lnf_g    = (const float*)d_in[20];
  const float* lnf_b    = (const float*)d_in[21];

  cudaFuncSetAttribute((const void*)a1w2f_k, cudaFuncAttributeMaxDynamicSharedMemorySize, DSM_A1W2F);

  float* base = nullptr;
  cudaGetSymbolAddress((void**)&base, g_scratch);

  static cudaStream_t sB = nullptr, sC = nullptr;
  static cudaEvent_t eF1, eJ1, eC1, eF2, eJ2, eC2;
  if (!sB){
    cudaStreamCreateWithFlags(&sB, cudaStreamNonBlocking);
    cudaStreamCreateWithFlags(&sC, cudaStreamNonBlocking);
    cudaEventCreateWithFlags(&eF1, cudaEventDisableTiming);
    cudaEventCreateWithFlags(&eJ1, cudaEventDisableTiming);
    cudaEventCreateWithFlags(&eC1, cudaEventDisableTiming);
    cudaEventCreateWithFlags(&eF2, cudaEventDisableTiming);
    cudaEventCreateWithFlags(&eJ2, cudaEventDisableTiming);
    cudaEventCreateWithFlags(&eC2, cudaEventDisableTiming);
  }

  float* hA = base + OFF_HA;
  float* hB = base + OFF_HB;

  roundh_copy_k<<<(unsigned)(((long)CDIM*KQKV+255)/256),256>>>(qkv1_w, (__half*)(base + OFF_W1R), (long)CDIM*KQKV);
  roundh_copy_k<<<(unsigned)(((long)CDIM*CDIM+255)/256),256>>>(out1_w, (__half*)(base + OFF_O1R), (long)CDIM*CDIM);
  roundh_copy_k<<<(unsigned)(((long)CDIM*KQKV+255)/256),256>>>(qkv2_w, (__half*)(base + OFF_W2R), (long)CDIM*KQKV);
  roundh_copy_k<<<(unsigned)(((long)CDIM*CDIM+255)/256),256>>>(out2_w, (__half*)(base + OFF_O2R), (long)CDIM*CDIM);

  init_h_k<<<(unsigned)((SZ_H + 255)/256), 256>>>(features, cls, hA);
  zero_k<<<(unsigned)(((long)PADN*CDIM/2 + 255)/256), 256>>>(base + OFF_LNX, (long)PADN*CDIM/2);

  run_attn_block(base, hA, ln1_g, ln1_b, (__half*)(base + OFF_W1R), (__half*)(base + OFF_O1R),
                 out1_b, res1_w, sB, sC, eF1, eJ1, eC1);

  build_wc_k<<<CDIM, 49>>>(w7, w5, w3, base + OFF_WC);
  cls_copy_k<<<1,256>>>(hA, hB);
  ppeg_k<<<dim3(2500, 4), 128>>>(hA, hB, base + OFF_WC, b7, b5, b3);

  run_attn_block(base, hB, ln2_g, ln2_b, (__half*)(base + OFF_W2R), (__half*)(base + OFF_O2R),
                 out2_b, res2_w, sB, sC, eF2, eJ2, eC2);

  ln_k<<<NTOK, 128>>>(hB, (float*)d_out, lnf_g, lnf_b);
}

// round 17
// speedup vs baseline: 1.5576x; 1.1296x over previous
#include <cuda_runtime.h>
#include <cuda_fp16.h>
#include <cstdint>
#include <mma.h>
using namespace nvcuda;

#define NTOK 10001
#define CDIM 512
#define NP   10240
#define PADN 239
#define NH   8
#define DH   64
#define NL   256
#define LW   40
#define KQKV (3*CDIM)
#define MPAD 10112

constexpr long SZ_H    = (long)NTOK*CDIM;
constexpr long SZ_LNX  = (long)NP*CDIM;
constexpr long SZ_QKV  = (long)NP*KQKV;
constexpr long SZ_LAND = (long)NH*NL*DH;
constexpr long SZ_A1   = (long)NH*NP*NL;
constexpr long SZ_A2   = (long)NH*NL*NL;

constexpr long OFF_HA   = 0;
constexpr long OFF_HB   = OFF_HA  + SZ_H;
constexpr long OFF_LNX  = OFF_HB  + SZ_H;
constexpr long OFF_QKV  = OFF_LNX + SZ_LNX;
constexpr long OFF_QL   = OFF_QKV + SZ_QKV;
constexpr long OFF_KL   = OFF_QL  + SZ_LAND;
constexpr long OFF_A1   = OFF_KL  + SZ_LAND;
constexpr long OFF_ATTH = OFF_A1;              // half[NP*CDIM]
constexpr long OFF_A3   = OFF_A1  + SZ_A1;     // half[NH*NL*NP]
constexpr long OFF_A2   = OFF_A3  + SZ_A1;
constexpr long OFF_ZA   = OFF_A2  + SZ_A2;     // half: a2h + tbh
constexpr long OFF_ZB   = OFF_ZA  + SZ_A2;     // half: zAh + zBh
constexpr long OFF_XZ   = OFF_ZB  + SZ_A2;     // half: xzh + ubh
constexpr long OFF_TB   = OFF_XZ  + SZ_A2;
constexpr long OFF_UB   = OFF_TB  + SZ_A2;
constexpr long OFF_CS   = OFF_UB  + SZ_A2;
constexpr long OFF_RS   = OFF_CS  + 2048;
constexpr long OFF_SC   = OFF_RS  + 2048;
constexpr long OFF_A3VP = OFF_SC  + 8;
constexpr long SZ_A3VP  = (long)NH*32*NL*DH;
constexpr long OFF_A3V  = OFF_A3VP + SZ_A3VP;
constexpr long OFF_W2   = OFF_A3V + SZ_LAND;
constexpr long OFF_ATT  = OFF_W2  + SZ_LAND;
constexpr long OFF_TMP  = OFF_ATT + SZ_LNX;
constexpr long OFF_WC   = OFF_TMP + (long)MPAD*CDIM;
constexpr long OFF_CNT  = OFF_WC + 512*49;
constexpr long OFF_W1R  = OFF_CNT + 256;
constexpr long OFF_O1R  = OFF_W1R + (long)CDIM*KQKV;
constexpr long OFF_W2R  = OFF_O1R + (long)CDIM*CDIM;
constexpr long OFF_O2R  = OFF_W2R + (long)CDIM*KQKV;
constexpr long OFF_M3   = OFF_O2R + (long)CDIM*CDIM;
constexpr long OFF_I3   = OFF_M3 + 2048;
constexpr long SCRATCH_SZ = OFF_I3 + 2048 + 64;

static __device__ float g_scratch[SCRATCH_SZ];

__device__ __forceinline__ float tf32r(float x){
  unsigned int u;
  asm("cvt.rna.tf32.f32 %0, %1;\n" : "=r"(u) : "f"(x));
  return __uint_as_float(u);
}

__device__ __forceinline__ float warpMax(float v){
  #pragma unroll
  for (int o=16;o;o>>=1) v = fmaxf(v, __shfl_xor_sync(0xffffffffu, v, o));
  return v;
}
__device__ __forceinline__ float warpSum(float v){
  #pragma unroll
  for (int o=16;o;o>>=1) v += __shfl_xor_sync(0xffffffffu, v, o);
  return v;
}

__device__ __forceinline__ void cp16g(void* dst, const void* src, bool ok){
  unsigned int d = (unsigned int)__cvta_generic_to_shared(dst);
  int b = ok ? 16 : 0;
  asm volatile("cp.async.cg.shared.global [%0], [%1], 16, %2;\n" :: "r"(d), "l"(src), "r"(b));
}

__global__ void roundh_copy_k(const float* __restrict__ in, __half* __restrict__ out, long n){
  long i = (long)blockIdx.x*256 + threadIdx.x;
  if (i < n) out[i] = __float2half_rn(in[i]);
}

__global__ void init_h_k(const float* __restrict__ feat, const float* __restrict__ cls,
                         float* __restrict__ h){
  long i = (long)blockIdx.x*256 + threadIdx.x;
  if (i >= SZ_H) return;
  h[i] = (i < CDIM) ? cls[i] : feat[i - CDIM];
}

__global__ void zero_k(float* __restrict__ p, long n){
  long i = (long)blockIdx.x*256 + threadIdx.x;
  if (i < n) p[i] = 0.f;
}

__global__ void ln_h_k(const float* __restrict__ x, __half* __restrict__ y,
                       const float* __restrict__ g, const float* __restrict__ b){
  const int t = blockIdx.x;
  const float* xr = x + (long)t*CDIM;
  __half* yr = y + (long)t*CDIM;
  int tid = threadIdx.x;
  float s = 0.f, s2 = 0.f;
  #pragma unroll
  for (int c = tid; c < CDIM; c += 128){ float v = xr[c]; s += v; s2 += v*v; }
  #pragma unroll
  for (int o=16;o;o>>=1){ s += __shfl_xor_sync(0xffffffffu,s,o); s2 += __shfl_xor_sync(0xffffffffu,s2,o); }
  __shared__ float sm[4], sm2[4];
  if ((tid&31)==0){ sm[tid>>5]=s; sm2[tid>>5]=s2; }
  __syncthreads();
  s  = sm[0]+sm[1]+sm[2]+sm[3];
  s2 = sm2[0]+sm2[1]+sm2[2]+sm2[3];
  float mu  = s * (1.f/CDIM);
  float var = s2 * (1.f/CDIM) - mu*mu;
  float inv = rsqrtf(var + 1e-5f);
  #pragma unroll
  for (int c = tid; c < CDIM; c += 128)
    yr[c] = __float2half_rn((xr[c]-mu)*inv*g[c] + b[c]);
}

__global__ void ln_k(const float* __restrict__ x, float* __restrict__ y,
                     const float* __restrict__ g, const float* __restrict__ b){
  const int t = blockIdx.x;
  const float* xr = x + (long)t*CDIM;
  float* yr = y + (long)t*CDIM;
  int tid = threadIdx.x;
  float s = 0.f, s2 = 0.f;
  #pragma unroll
  for (int c = tid; c < CDIM; c += 128){ float v = xr[c]; s += v; s2 += v*v; }
  #pragma unroll
  for (int o=16;o;o>>=1){ s += __shfl_xor_sync(0xffffffffu,s,o); s2 += __shfl_xor_sync(0xffffffffu,s2,o); }
  __shared__ float sm[4], sm2[4];
  if ((tid&31)==0){ sm[tid>>5]=s; sm2[tid>>5]=s2; }
  __syncthreads();
  s  = sm[0]+sm[1]+sm[2]+sm[3];
  s2 = sm2[0]+sm2[1]+sm2[2]+sm2[3];
  float mu  = s * (1.f/CDIM);
  float var = s2 * (1.f/CDIM) - mu*mu;
  float inv = rsqrtf(var + 1e-5f);
  #pragma unroll
  for (int c = tid; c < CDIM; c += 128)
    yr[c] = (xr[c]-mu)*inv*g[c] + b[c];
}

// ---------- fp16 tensor-core GEMM, fp32 accumulate, 2-stage cp.async ----------
template<int BN, bool NT, bool HOUT>
__global__ void __launch_bounds__(256,2) gemm16(
                        const __half* __restrict__ A, int lda, long sA,
                        const __half* __restrict__ B, int ldb, long sB,
                        void* __restrict__ Cv, int ldc, long sC,
                        int M, int N, int K, float alpha)
{
  constexpr int BM=128, BK=32, BKP=40, BNPH=BN+8;
  constexpr int WN = BN/2, NF = WN/16;
  constexpr int ASZ = BM*BKP;
  constexpr int BSZ = NT ? BN*BKP : BK*BNPH;
  extern __shared__ __half dynh[];
  __half* Asm = dynh;
  __half* Bsm = dynh + 2*ASZ;

  const int tid = threadIdx.x;
  const int wid = tid >> 5;
  const int warp_m = wid & 3, warp_n = wid >> 2;
  const int bm = blockIdx.y*BM, bn = blockIdx.x*BN;
  A += (long)blockIdx.z * sA;
  B += (long)blockIdx.z * sB;

  wmma::fragment<wmma::accumulator,16,16,16,float> acc[2][NF];
  #pragma unroll
  for (int im=0;im<2;im++)
    #pragma unroll
    for (int jn=0;jn<NF;jn++) wmma::fill_fragment(acc[im][jn], 0.f);

  auto loadA = [&](int s, int k0){
    __half* As = Asm + s*ASZ;
    #pragma unroll
    for (int i=0;i<2;i++){
      int lin = tid + i*256;
      int r = lin >> 2, k8 = (lin & 3)*8;
      int gr = bm + r;
      bool ok = gr < M;
      const __half* src = A + (long)(ok ? gr : bm)*lda + k0 + k8;
      cp16g(As + r*BKP + k8, src, ok);
    }
  };
  auto loadB = [&](int s, int k0){
    __half* Bs = Bsm + s*BSZ;
    if (!NT){
      constexpr int NCH = (BK*BN/8)/256;
      #pragma unroll
      for (int i=0;i<NCH;i++){
        int lin = tid + i*256;
        int kk = lin / (BN/8), c8 = (lin % (BN/8))*8;
        cp16g(Bs + kk*BNPH + c8, B + (long)(k0+kk)*ldb + bn + c8, true);
      }
    } else {
      constexpr int NCH = (BN*BK/8)/256;
      #pragma unroll
      for (int i=0;i<NCH;i++){
        int lin = tid + i*256;
        int c = lin >> 2, k8 = (lin & 3)*8;
        cp16g(Bs + c*BKP + k8, B + (long)(bn+c)*ldb + k0 + k8, true);
      }
    }
  };

  const int nt = K/BK;
  loadA(0, 0); loadB(0, 0);
  asm volatile("cp.async.commit_group;\n");
  for (int t=0; t<nt; t++){
    int cs = t & 1;
    if (t+1 < nt){
      loadA((t+1)&1, (t+1)*BK);
      loadB((t+1)&1, (t+1)*BK);
      asm volatile("cp.async.commit_group;\n");
      asm volatile("cp.async.wait_group 1;\n");
    } else {
      asm volatile("cp.async.wait_group 0;\n");
    }
    __syncthreads();
    __half* As = Asm + cs*ASZ;
    __half* Bs = Bsm + cs*BSZ;
    #pragma unroll
    for (int kk=0; kk<BK; kk+=16){
      wmma::fragment<wmma::matrix_a,16,16,16,__half,wmma::row_major> af[2];
      #pragma unroll
      for (int im=0;im<2;im++)
        wmma::load_matrix_sync(af[im], As + (warp_m*32 + im*16)*BKP + kk, BKP);
      if (!NT){
        wmma::fragment<wmma::matrix_b,16,16,16,__half,wmma::row_major> bf[NF];
        #pragma unroll
        for (int jn=0;jn<NF;jn++)
          wmma::load_matrix_sync(bf[jn], Bs + kk*BNPH + warp_n*WN + jn*16, BNPH);
        #pragma unroll
        for (int im=0;im<2;im++)
          #pragma unroll
          for (int jn=0;jn<NF;jn++)
            wmma::mma_sync(acc[im][jn], af[im], bf[jn], acc[im][jn]);
      } else {
        wmma::fragment<wmma::matrix_b,16,16,16,__half,wmma::col_major> bf[NF];
        #pragma unroll
        for (int jn=0;jn<NF;jn++)
          wmma::load_matrix_sync(bf[jn], Bs + (warp_n*WN + jn*16)*BKP + kk, BKP);
        #pragma unroll
        for (int im=0;im<2;im++)
          #pragma unroll
          for (int jn=0;jn<NF;jn++)
            wmma::mma_sync(acc[im][jn], af[im], bf[jn], acc[im][jn]);
      }
    }
    __syncthreads();
  }
  #pragma unroll
  for (int im=0;im<2;im++)
    #pragma unroll
    for (int jn=0;jn<NF;jn++)
      #pragma unroll
      for (int e=0;e<acc[im][jn].num_elements;e++)
        acc[im][jn].x[e] *= alpha;

  if (!HOUT){
    float* C = (float*)Cv + (long)blockIdx.z * sC;
    #pragma unroll
    for (int im=0;im<2;im++)
      #pragma unroll
      for (int jn=0;jn<NF;jn++){
        int gr = bm + warp_m*32 + im*16;
        if (gr < M)
          wmma::store_matrix_sync(C + (long)gr*ldc + bn + warp_n*WN + jn*16,
                                  acc[im][jn], ldc, wmma::mem_row_major);
      }
  } else {
    __half* C = (__half*)Cv + (long)blockIdx.z * sC;
    float* stg = (float*)dynh;
    constexpr int BNP4 = BN+4;
    __syncthreads();
    #pragma unroll
    for (int phase=0; phase<2; phase++){
      if ((warp_m >> 1) == phase){
        int rloc = (warp_m & 1)*32;
        #pragma unroll
        for (int im=0;im<2;im++)
          #pragma unroll
          for (int jn=0;jn<NF;jn++)
            wmma::store_matrix_sync(stg + (rloc + im*16)*BNP4 + warp_n*WN + jn*16,
                                    acc[im][jn], BNP4, wmma::mem_row_major);
      }
      __syncthreads();
      constexpr int NCH = (64*BN/8)/256;
      #pragma unroll
      for (int i=0;i<NCH;i++){
        int lin = tid + i*256;
        int r = lin / (BN/8), c8 = (lin % (BN/8))*8;
        int gr = bm + phase*64 + r;
        if (gr < M){
          const float* sp = stg + r*BNP4 + c8;
          __half2 h0 = __floats2half2_rn(sp[0], sp[1]);
          __half2 h1 = __floats2half2_rn(sp[2], sp[3]);
          __half2 h2 = __floats2half2_rn(sp[4], sp[5]);
          __half2 h3 = __floats2half2_rn(sp[6], sp[7]);
          __half2* dp = (__half2*)(C + (long)gr*ldc + bn + c8);
          dp[0]=h0; dp[1]=h1; dp[2]=h2; dp[3]=h3;
        }
      }
      __syncthreads();
    }
  }
}

constexpr int DSM16_NN128 = (2*(128*40) + 2*(32*136))*2;
constexpr int DSM16_NT128 = (2*(128*40) + 2*(128*40))*2;
constexpr int DSM16_NN64  = (2*(128*40) + 2*(32*72))*2;

__global__ void landmarks_k(const __half* __restrict__ qkv,
                            __half* __restrict__ ql, __half* __restrict__ kl){
  int j = blockIdx.x, h = blockIdx.y, d = threadIdx.x;
  const __half* base = qkv + (long)(j*LW)*KQKV + h*DH + d;
  float sq = 0.f, sk = 0.f;
  #pragma unroll 8
  for (int t=0;t<LW;t++){
    sq += __half2float(base[(long)t*KQKV]);
    sk += __half2float(base[(long)t*KQKV + CDIM]);
  }
  long o = ((long)h*NL + j)*DH + d;
  ql[o] = __float2half_rn(sq * (1.f/LW));
  kl[o] = __float2half_rn(sk * (1.f/LW));
}

__global__ void softmax256(float* __restrict__ x){
  float* p = x + (long)blockIdx.x * NL;
  int tid = threadIdx.x;
  float v = p[tid];
  __shared__ float sm[8];
  float m = warpMax(v);
  if ((tid&31)==0) sm[tid>>5]=m;
  __syncthreads();
  if (tid < 32){ float t = (tid<8)? sm[tid] : -3.4e38f; t = warpMax(t); if (tid==0) sm[0]=t; }
  __syncthreads();
  m = sm[0];
  __syncthreads();
  float e = __expf(v - m);
  float s = warpSum(e);
  if ((tid&31)==0) sm[tid>>5]=s;
  __syncthreads();
  if (tid < 32){ float t = (tid<8)? sm[tid] : 0.f; t = warpSum(t); if (tid==0) sm[0]=t; }
  __syncthreads();
  p[tid] = e / sm[0];
}

// per-row max + invsum of raw sim3 (half)
__global__ void rowstat3_k(const __half* __restrict__ a3, float* __restrict__ m3,
                           float* __restrict__ i3){
  int r = blockIdx.x, h = blockIdx.y, tid = threadIdx.x;
  const __half* p = a3 + ((long)h*NL + r)*NP;
  float va[NP/256];
  float m = -3.4e38f;
  #pragma unroll
  for (int i=0;i<NP/256;i++){ va[i] = __half2float(p[tid + i*256]); m = fmaxf(m, va[i]); }
  __shared__ float sm[8];
  m = warpMax(m);
  if ((tid&31)==0) sm[tid>>5]=m;
  __syncthreads();
  if (tid < 32){ float t = (tid<8)? sm[tid] : -3.4e38f; t = warpMax(t); if (tid==0) sm[0]=t; }
  __syncthreads();
  m = sm[0];
  __syncthreads();
  float s = 0.f;
  #pragma unroll
  for (int i=0;i<NP/256;i++) s += __expf(va[i]-m);
  s = warpSum(s);
  if ((tid&31)==0) sm[tid>>5]=s;
  __syncthreads();
  if (tid < 32){ float t = (tid<8)? sm[tid] : 0.f; t = warpSum(t); if (tid==0) sm[0]=t; }
  __syncthreads();
  if (tid==0){ m3[h*NL+r]=m; i3[h*NL+r]=1.f/sm[0]; }
}

__global__ void colsum_k(const float* __restrict__ a2, float* __restrict__ cs){
  int row = blockIdx.x*256 + threadIdx.x;
  const float* p = a2 + (long)row*NL;
  float s = 0.f;
  for (int j=0;j<NL;j++) s += fabsf(p[j]);
  cs[row] = s;
}
__global__ void rowsum_k(const float* __restrict__ a2, float* __restrict__ rs){
  int h = blockIdx.x, j = threadIdx.x;
  float s = 0.f;
  for (int i=0;i<NL;i++) s += fabsf(a2[((long)h*NL + i)*NL + j]);
  rs[h*NL + j] = s;
}
__global__ void maxmul_k(const float* __restrict__ cs, const float* __restrict__ rs,
                         float* __restrict__ sc){
  int tid = threadIdx.x;
  float mc = -3.4e38f, mr = -3.4e38f;
  for (int i = tid; i < NH*NL; i += 256){ mc = fmaxf(mc, cs[i]); mr = fmaxf(mr, rs[i]); }
  __shared__ float sa[8], sb[8];
  mc = warpMax(mc); mr = warpMax(mr);
  if ((tid&31)==0){ sa[tid>>5]=mc; sb[tid>>5]=mr; }
  __syncthreads();
  if (tid < 32){
    float a = (tid<8)? sa[tid] : -3.4e38f;
    float b = (tid<8)? sb[tid] : -3.4e38f;
    a = warpMax(a); b = warpMax(b);
    if (tid==0) sc[0] = a*b;
  }
}

// ---------- persistent pinv in fp16 ----------
struct PinvSmem16 { __half As[64][40]; __half Bs[32][264]; float stg[8][16][18]; };

__device__ __forceinline__ void head_bar(int* c, int tid){
  __syncthreads();
  if (tid == 0){
    __threadfence();
    atomicAdd(c, 1);
    while (atomicAdd(c, 0) < 4) __nanosleep(32);
    __threadfence();
  }
  __syncthreads();
}

// O[rb*64..+64)[0..256) = L @ B', B' = tr ? (beta*R + alphaD*I) : R  (256x256 half row-major)
__device__ void pinv_mm16(const __half* __restrict__ L, const __half* __restrict__ R,
                          __half* __restrict__ O, int rb, float beta, float alphaD, bool tr,
                          PinvSmem16* s)
{
  int tid = threadIdx.x, wid = tid>>5, lane = tid&31;
  int wm = wid & 1, wn = wid >> 1;
  wmma::fragment<wmma::accumulator,16,16,16,float> acc[2][4];
  #pragma unroll
  for (int im=0;im<2;im++)
    #pragma unroll
    for (int jn=0;jn<4;jn++) wmma::fill_fragment(acc[im][jn], 0.f);

  for (int k0=0; k0<NL; k0+=32){
    {
      int r = tid >> 2, k8 = (tid & 3)*8;
      uint4 v = __ldcg((const uint4*)&L[(long)(rb*64+r)*NL + k0 + k8]);
      *(uint4*)&s->As[r][k8] = v;
    }
    #pragma unroll
    for (int i=0;i<4;i++){
      int lin = tid + i*256;
      int kk = lin >> 5, c8 = (lin & 31)*8;
      uint4 raw = __ldcg((const uint4*)&R[(long)(k0+kk)*NL + c8]);
      if (tr){
        __half2* hp = (__half2*)&raw;
        int gk = k0 + kk;
        #pragma unroll
        for (int u=0;u<4;u++){
          float2 f = __half22float2(hp[u]);
          int cc = c8 + 2*u;
          f.x = beta*f.x + ((gk==cc  ) ? alphaD : 0.f);
          f.y = beta*f.y + ((gk==cc+1) ? alphaD : 0.f);
          hp[u] = __floats2half2_rn(f.x, f.y);
        }
      }
      *(uint4*)&s->Bs[kk][c8] = raw;
    }
    __syncthreads();
    #pragma unroll
    for (int kk=0; kk<32; kk+=16){
      wmma::fragment<wmma::matrix_a,16,16,16,__half,wmma::row_major> af[2];
      wmma::fragment<wmma::matrix_b,16,16,16,__half,wmma::row_major> bf[4];
      #pragma unroll
      for (int im=0;im<2;im++)
        wmma::load_matrix_sync(af[im], &s->As[wm*32 + im*16][kk], 40);
      #pragma unroll
      for (int jn=0;jn<4;jn++)
        wmma::load_matrix_sync(bf[jn], &s->Bs[kk][wn*64 + jn*16], 264);
      #pragma unroll
      for (int im=0;im<2;im++)
        #pragma unroll
        for (int jn=0;jn<4;jn++)
          wmma::mma_sync(acc[im][jn], af[im], bf[jn], acc[im][jn]);
    }
    __syncthreads();
  }
  // epilogue: per-warp staging, half store
  #pragma unroll
  for (int im=0;im<2;im++)
    #pragma unroll
    for (int jn=0;jn<4;jn++){
      wmma::store_matrix_sync(&s->stg[wid][0][0], acc[im][jn], 18, wmma::mem_row_major);
      __syncwarp();
      #pragma unroll
      for (int u=0;u<8;u++){
        int idx = lane*8 + u;
        int rr = idx >> 4, cc = idx & 15;
        O[(long)(rb*64 + wm*32 + im*16 + rr)*NL + wn*64 + jn*16 + cc] =
            __float2half_rn(s->stg[wid][rr][cc]);
      }
      __syncwarp();
    }
}

__global__ void pinv16_k(const float* __restrict__ a2f, __half* __restrict__ a2h_f,
                         __half* __restrict__ zAf, __half* __restrict__ zBf,
                         __half* __restrict__ xzf, __half* __restrict__ ubf,
                         __half* __restrict__ tbf,
                         const float* __restrict__ sc, int* __restrict__ cnt)
{
  __shared__ PinvSmem16 s;
  int rb = blockIdx.x, h = blockIdx.y, tid = threadIdx.x;
  const long HS = (long)h*NL*NL;
  const float* a2 = a2f + HS;
  __half* A2H = a2h_f + HS;
  __half* ZA = zAf + HS; __half* ZB = zBf + HS;
  __half* XZ = xzf + HS; __half* UB = ubf + HS; __half* TB = tbf + HS;
  int* c = cnt + h*32;

  float inv = 1.f / sc[0];
  for (int idx = tid; idx < 64*NL; idx += 256){
    int i = rb*64 + (idx >> 8), j = idx & 255;
    ZA[(long)i*NL + j]  = __float2half_rn(__ldcg(&a2[(long)j*NL + i]) * inv);
    A2H[(long)i*NL + j] = __float2half_rn(__ldcg(&a2[(long)i*NL + j]));
  }
  int step = 0;
  head_bar(c + step++, tid);

  __half* cur = ZA; __half* nxt = ZB;
  for (int it=0; it<6; ++it){
    pinv_mm16(A2H, cur, XZ, rb, 0.f, 0.f, false, &s);       head_bar(c + step++, tid);
    pinv_mm16(XZ, XZ, UB, rb, -1.f, 7.f, true, &s);         head_bar(c + step++, tid);
    pinv_mm16(XZ, UB, TB, rb, -1.f, 15.f, true, &s);        head_bar(c + step++, tid);
    pinv_mm16(cur, TB, nxt, rb, -0.25f, 3.25f, true, &s);   head_bar(c + step++, tid);
    __half* t = cur; cur = nxt; nxt = t;
  }
}

// a3v with softmax folded in; a3 and v half
__global__ void a3v_partial_k(const __half* __restrict__ a3, const __half* __restrict__ qkv,
                              const float* __restrict__ m3, const float* __restrict__ i3,
                              float* __restrict__ part){
  int ch = blockIdx.x, h = blockIdx.y;
  int tid = threadIdx.x;
  __shared__ float a3s[256][33];
  __shared__ float vs[32][DH];
  __shared__ float m3s[256], i3s[256];
  m3s[tid] = m3[h*NL + tid];
  i3s[tid] = i3[h*NL + tid];
  __syncthreads();
  float acc[DH];
  #pragma unroll
  for (int d=0;d<DH;d++) acc[d]=0.f;
  int k0base = ch * (NP/32);
  for (int kk0 = 0; kk0 < NP/32; kk0 += 32) {
    int kbase = k0base + kk0;
    #pragma unroll
    for (int idx = tid; idx < 256*32; idx += 256) {
      int r = idx >> 5, k = idx & 31;
      float raw = __half2float(a3[((long)h*NL + r)*NP + kbase + k]);
      a3s[r][k] = __expf(raw - m3s[r]) * i3s[r];
    }
    #pragma unroll
    for (int idx = tid; idx < 32*DH; idx += 256) {
      int k = idx >> 6, d = idx & 63;
      vs[k][d] = __half2float(qkv[(long)(kbase+k)*KQKV + 2*CDIM + h*DH + d]);
    }
    __syncthreads();
    #pragma unroll 4
    for (int k=0;k<32;k++){
      float pp = a3s[tid][k];
      #pragma unroll
      for (int d=0;d<DH;d++) acc[d] = fmaf(pp, vs[k][d], acc[d]);
    }
    __syncthreads();
  }
  float* o = part + (((long)h*32 + ch)*NL + tid)*DH;
  #pragma unroll
  for (int d=0;d<DH;d++) o[d] = acc[d];
}
__global__ void a3v_reduce_k(const float* __restrict__ part, __half* __restrict__ out){
  int idx = blockIdx.x*256 + threadIdx.x;
  int h = idx >> 14;
  int rem = idx & 16383;
  float s = 0.f;
  #pragma unroll
  for (int ch=0; ch<32; ch++)
    s += part[(((long)h*32 + ch) << 14) + rem];
  out[idx] = __float2half_rn(s);
}

// ---- fused fp16: S = q@kl^T ; softmax(0.125*S) ; atth = (att + Sh @ Wh) as half ----
#define SLD 260
#define SLDH 264
__global__ void __launch_bounds__(256,1) a1w2f_k(const __half* __restrict__ qkv,
                                                 const __half* __restrict__ kl,
                                                 const float* __restrict__ w2,
                                                 const float* __restrict__ att,
                                                 __half* __restrict__ atth){
  extern __shared__ float sm_[];
  float*  S   = sm_;
  __half* QH  = (__half*)(sm_ + 128*SLD);
  __half* KLH = QH + 128*72;
  __half* WH  = QH;
  __half* Sh  = (__half*)sm_;
  int tid = threadIdx.x;
  int h = blockIdx.y;
  long rowbase = (long)blockIdx.x*128;
  int wid = tid>>5;

  #pragma unroll
  for (int i=0;i<4;i++){
    int lin = tid + i*256;
    int r = lin >> 3, c8 = (lin & 7)*8;
    *(uint4*)&QH[r*72 + c8] = *(const uint4*)&qkv[(rowbase + r)*KQKV + h*DH + c8];
  }

  {
    int wm = wid & 3, wn = wid >> 2;
    for (int half_=0; half_<2; half_++){
      #pragma unroll
      for (int i=0;i<4;i++){
        int lin = tid + i*256;
        int r = lin >> 3, c8 = (lin & 7)*8;
        *(uint4*)&KLH[r*72 + c8] = *(const uint4*)&kl[((long)h*NL + half_*128 + r)*DH + c8];
      }
      __syncthreads();
      wmma::fragment<wmma::accumulator,16,16,16,float> acc[2][4];
      #pragma unroll
      for (int im=0;im<2;im++)
        #pragma unroll
        for (int jn=0;jn<4;jn++) wmma::fill_fragment(acc[im][jn], 0.f);
      #pragma unroll
      for (int k0=0;k0<DH;k0+=16){
        wmma::fragment<wmma::matrix_a,16,16,16,__half,wmma::row_major> af[2];
        wmma::fragment<wmma::matrix_b,16,16,16,__half,wmma::col_major> bf[4];
        #pragma unroll
        for (int im=0;im<2;im++)
          wmma::load_matrix_sync(af[im], QH + (wm*32 + im*16)*72 + k0, 72);
        #pragma unroll
        for (int jn=0;jn<4;jn++)
          wmma::load_matrix_sync(bf[jn], KLH + (wn*64 + jn*16)*72 + k0, 72);
        #pragma unroll
        for (int im=0;im<2;im++)
          #pragma unroll
          for (int jn=0;jn<4;jn++)
            wmma::mma_sync(acc[im][jn], af[im], bf[jn], acc[im][jn]);
      }
      #pragma unroll
      for (int im=0;im<2;im++)
        #pragma unroll
        for (int jn=0;jn<4;jn++)
          wmma::store_matrix_sync(S + (long)(wm*32 + im*16)*SLD + half_*128 + wn*64 + jn*16,
                                  acc[im][jn], SLD, wmma::mem_row_major);
      __syncthreads();
    }
  }

  #pragma unroll
  for (int i=0;i<8;i++){
    int lin = tid + i*256;
    int r = lin >> 3, c8 = (lin & 7)*8;
    const float* sp = &w2[(long)h*NL*DH + r*DH + c8];
    __half2* dp = (__half2*)&WH[r*72 + c8];
    dp[0] = __floats2half2_rn(sp[0], sp[1]);
    dp[1] = __floats2half2_rn(sp[2], sp[3]);
    dp[2] = __floats2half2_rn(sp[4], sp[5]);
    dp[3] = __floats2half2_rn(sp[6], sp[7]);
  }
  {
    int r = tid >> 1, hf = tid & 1;
    float* Sr = S + r*SLD + hf*128;
    float m = -3.4e38f;
    #pragma unroll
    for (int j=0;j<128;j++) m = fmaxf(m, Sr[j]);
    m = fmaxf(m, __shfl_xor_sync(0xffffffffu, m, 1));
    float s = 0.f;
    #pragma unroll
    for (int j=0;j<128;j++){ float e = __expf(0.125f*(Sr[j]-m)); Sr[j]=e; s += e; }
    s += __shfl_xor_sync(0xffffffffu, s, 1);
    float inv = 1.f/s;
    #pragma unroll
    for (int j=0;j<128;j++) Sr[j] = Sr[j]*inv;
  }
  __syncthreads();
  {
    #pragma unroll
    for (int c=0; c<32768; c+=1024){
      int e = c + tid*4;
      int r = e >> 8, j = e & 255;
      float4 v = *(float4*)&S[(long)r*SLD + j];
      __syncthreads();
      __half2* d = (__half2*)(Sh + (long)r*SLDH + j);
      d[0] = __floats2half2_rn(v.x, v.y);
      d[1] = __floats2half2_rn(v.z, v.w);
      __syncthreads();
    }
  }

  // phase 3: acc = att_tile (conv) + Sh @ WH ; store half via staging
  {
    int wm = wid & 3, wn = wid >> 2;
    wmma::fragment<wmma::accumulator,16,16,16,float> acc[2][2];
    #pragma unroll
    for (int im=0;im<2;im++)
      #pragma unroll
      for (int jn=0;jn<2;jn++)
        wmma::load_matrix_sync(acc[im][jn],
            att + (rowbase + wm*32 + im*16)*CDIM + h*DH + wn*32 + jn*16,
            CDIM, wmma::mem_row_major);
    #pragma unroll
    for (int k0=0;k0<NL;k0+=16){
      wmma::fragment<wmma::matrix_a,16,16,16,__half,wmma::row_major> af[2];
      wmma::fragment<wmma::matrix_b,16,16,16,__half,wmma::row_major> bf[2];
      #pragma unroll
      for (int im=0;im<2;im++)
        wmma::load_matrix_sync(af[im], Sh + (long)(wm*32 + im*16)*SLDH + k0, SLDH);
      #pragma unroll
      for (int jn=0;jn<2;jn++)
        wmma::load_matrix_sync(bf[jn], WH + k0*72 + wn*32 + jn*16, 72);
      #pragma unroll
      for (int im=0;im<2;im++)
        #pragma unroll
        for (int jn=0;jn<2;jn++)
          wmma::mma_sync(acc[im][jn], af[im], bf[jn], acc[im][jn]);
    }
    __syncthreads();                       // Sh reads done; reuse as float staging
    float* stg = sm_;                      // [128][68]
    #pragma unroll
    for (int im=0;im<2;im++)
      #pragma unroll
      for (int jn=0;jn<2;jn++)
        wmma::store_matrix_sync(stg + (wm*32 + im*16)*68 + wn*32 + jn*16,
                                acc[im][jn], 68, wmma::mem_row_major);
    __syncthreads();
    #pragma unroll
    for (int i=0;i<4;i++){
      int lin = tid + i*256;
      int r = lin >> 3, c8 = (lin & 7)*8;
      const float* sp = stg + r*68 + c8;
      __half2* dp = (__half2*)(atth + (rowbase + r)*CDIM + h*DH + c8);
      dp[0] = __floats2half2_rn(sp[0], sp[1]);
      dp[1] = __floats2half2_rn(sp[2], sp[3]);
      dp[2] = __floats2half2_rn(sp[4], sp[5]);
      dp[3] = __floats2half2_rn(sp[6], sp[7]);
    }
  }
}
constexpr int DSM_A1W2F = 128*SLD*4 + 256*72*2;

// conv initializes att (fp32), v read as half
__global__ void conv_res_k(const __half* __restrict__ qkv, const float* __restrict__ rw,
                           float* __restrict__ att){
  int idx = blockIdx.x*256 + threadIdx.x;
  int c  = idx & (CDIM-1);
  int ig = idx >> 9;
  int i0 = ig*8;
  const float* w = rw + (c>>6)*33;
  float wl[33];
  #pragma unroll
  for (int u=0;u<33;u++) wl[u] = w[u];
  float vb[40];
  #pragma unroll
  for (int u=0;u<40;u++){
    int r = i0 - 16 + u;
    vb[u] = (r>=0 && r<NP) ? __half2float(qkv[(long)r*KQKV + 2*CDIM + c]) : 0.f;
  }
  #pragma unroll
  for (int t=0;t<8;t++){
    float acc = 0.f;
    #pragma unroll
    for (int u=0;u<33;u++) acc = fmaf(wl[u], vb[t+u], acc);
    att[(long)(i0+t)*CDIM + c] = acc;
  }
}

__global__ void build_wc_k(const float* __restrict__ w7, const float* __restrict__ w5,
                           const float* __restrict__ w3, float* __restrict__ wc){
  int c = blockIdx.x, k = threadIdx.x;
  int ky = k/7, kx = k%7, dy = ky-3, dx = kx-3;
  float w = w7[c*49 + k];
  if (dy>=-2 && dy<=2 && dx>=-2 && dx<=2) w += w5[c*25 + (dy+2)*5 + (dx+2)];
  if (dy>=-1 && dy<=1 && dx>=-1 && dx<=1) w += w3[c*9  + (dy+1)*3 + (dx+1)];
  if (dy==0 && dx==0) w += 1.f;
  wc[k*CDIM + c] = w;
}

__global__ void cls_copy_k(const float* __restrict__ hin, float* __restrict__ hout){
  hout[threadIdx.x] = hin[threadIdx.x];
  hout[256+threadIdx.x] = hin[256+threadIdx.x];
}

__global__ void ppeg_k(const float* __restrict__ hin, float* __restrict__ hout,
                       const float* __restrict__ wc,
                       const float* __restrict__ b7, const float* __restrict__ b5,
                       const float* __restrict__ b3){
  int bx = blockIdx.x;
  int c  = blockIdx.y*128 + threadIdx.x;
  int y  = bx / 25;
  int xg = (bx % 25) * 4;
  float bsum = b7[c] + b5[c] + b3[c];
  float acc[4] = {bsum, bsum, bsum, bsum};
  #pragma unroll
  for (int ky=0; ky<7; ky++){
    int yy = y + ky - 3;
    bool vy = (yy>=0 && yy<100);
    #pragma unroll
    for (int dx=-3; dx<=6; dx++){
      int xx = xg + dx;
      float v = (vy && xx>=0 && xx<100) ? hin[(long)(1 + yy*100 + xx)*CDIM + c] : 0.f;
      #pragma unroll
      for (int j=0;j<4;j++){
        int kx = dx - j + 3;
        if (kx>=0 && kx<7) acc[j] = fmaf(wc[(ky*7+kx)*CDIM + c], v, acc[j]);
      }
    }
  }
  #pragma unroll
  for (int j=0;j<4;j++)
    hout[(long)(1 + y*100 + xg + j)*CDIM + c] = acc[j];
}

__global__ void addres_k(float* __restrict__ h, const float* __restrict__ tmp,
                         const float* __restrict__ bias){
  long idx = (long)blockIdx.x*256 + threadIdx.x;
  if (idx >= SZ_H) return;
  int c = (int)(idx & (CDIM-1));
  h[idx] += tmp[idx] + bias[c];
}

static void run_attn_block(float* base, float* h,
                           const float* lng, const float* lnb,
                           const __half* qkvwR, const __half* outwR, const float* outb,
                           const float* resw,
                           cudaStream_t sB, cudaStream_t sC,
                           cudaEvent_t eF, cudaEvent_t eJ, cudaEvent_t eC)
{
  __half* lnxh = (__half*)(base + OFF_LNX);
  __half* qkvh = (__half*)(base + OFF_QKV);
  __half* qlh  = (__half*)(base + OFF_QL);
  __half* klh  = (__half*)(base + OFF_KL);
  __half* atth = (__half*)(base + OFF_ATTH);
  __half* a3vh = (__half*)(base + OFF_A3V);
  __half* a3h  = (__half*)(base + OFF_A3);
  float* a2   = base + OFF_A2;
  __half* a2h = (__half*)(base + OFF_ZA);
  __half* tbh = a2h + SZ_A2;
  __half* zAh = (__half*)(base + OFF_ZB);
  __half* zBh = zAh + SZ_A2;
  __half* xzh = (__half*)(base + OFF_XZ);
  __half* ubh = xzh + SZ_A2;
  float* cs   = base + OFF_CS;
  float* rs   = base + OFF_RS;
  float* sc   = base + OFF_SC;
  float* a3vp = base + OFF_A3VP;
  float* w2   = base + OFF_W2;
  float* att  = base + OFF_ATT;
  float* tmp  = base + OFF_TMP;
  float* m3   = base + OFF_M3;
  float* i3   = base + OFF_I3;
  int*   cnt  = (int*)(base + OFF_CNT);

  ln_h_k<<<NTOK,128>>>(h, lnxh + (long)PADN*CDIM, lng, lnb);

  gemm16<128,false,true><<<dim3(KQKV/128, NP/128, 1), 256, DSM16_NN128>>>(
      lnxh, CDIM, 0, qkvwR, KQKV, 0, qkvh, KQKV, 0, NP, KQKV, CDIM, 1.f);

  landmarks_k<<<dim3(NL,NH), DH>>>(qkvh, qlh, klh);

  cudaEventRecord(eF, 0);
  cudaStreamWaitEvent(sB, eF, 0);
  cudaStreamWaitEvent(sC, eF, 0);

  conv_res_k<<<(NP/8)*CDIM/256, 256, 0, sC>>>(qkvh, resw, att);
  cudaEventRecord(eC, sC);

  gemm16<128,true,false><<<dim3(2, 2, NH), 256, DSM16_NT128, sB>>>(
      qlh, DH, (long)NL*DH, klh, DH, (long)NL*DH, a2, NL, (long)NL*NL, NL, NL, DH, 0.125f);
  softmax256<<<NH*NL, 256, 0, sB>>>(a2);
  colsum_k<<<8,256,0,sB>>>(a2, cs);
  rowsum_k<<<8,256,0,sB>>>(a2, rs);
  maxmul_k<<<1,256,0,sB>>>(cs, rs, sc);
  zero_k<<<1,256,0,sB>>>(base + OFF_CNT, 256);
  pinv16_k<<<dim3(4,NH), 256, 0, sB>>>(a2, a2h, zAh, zBh, xzh, ubh, tbh, sc, cnt);
  cudaEventRecord(eJ, sB);

  gemm16<128,true,true><<<dim3(NP/128, 2, NH), 256, DSM16_NT128>>>(
      qlh, DH, (long)NL*DH, qkvh + CDIM, KQKV, 64, a3h, NP, (long)NL*NP, NL, NP, DH, 0.125f);
  rowstat3_k<<<dim3(NL,NH), 256>>>(a3h, m3, i3);
  a3v_partial_k<<<dim3(32,NH),256>>>(a3h, qkvh, m3, i3, a3vp);
  a3v_reduce_k<<<(unsigned)((NH*NL*DH)/256),256>>>(a3vp, a3vh);

  cudaStreamWaitEvent(0, eJ, 0);
  gemm16<64,false,false><<<dim3(1,2,NH), 256, DSM16_NN64>>>(
      zAh, NL, (long)NL*NL, a3vh, DH, (long)NL*DH, w2, DH, (long)NL*DH, NL, DH, NL, 1.f);

  cudaStreamWaitEvent(0, eC, 0);
  a1w2f_k<<<dim3(NP/128, NH), 256, DSM_A1W2F>>>(qkvh, klh, w2, att, atth);

  gemm16<128,false,false><<<dim3(CDIM/128, MPAD/128, 1), 256, DSM16_NN128>>>(
      atth + (long)PADN*CDIM, CDIM, 0, outwR, CDIM, 0, tmp, CDIM, 0, NTOK, CDIM, CDIM, 1.f);
  addres_k<<<(unsigned)((SZ_H+255)/256),256>>>(h, tmp, outb);
}

extern "C" void kernel_launch(void* const* d_in, const int* in_sizes, int n_in,
                              void* d_out, int out_size)
{
  (void)in_sizes; (void)n_in; (void)out_size;
  const float* features = (const float*)d_in[0];
  const float* cls      = (const float*)d_in[1];
  const float* ln1_g    = (const float*)d_in[2];
  const float* ln1_b    = (const float*)d_in[3];
  const float* qkv1_w   = (const float*)d_in[4];
  const float* out1_w   = (const float*)d_in[5];
  const float* out1_b   = (const float*)d_in[6];
  const float* res1_w   = (const float*)d_in[7];
  const float* w7       = (const float*)d_in[8];
  const float* b7       = (const float*)d_in[9];
  const float* w5       = (const float*)d_in[10];
  const float* b5       = (const float*)d_in[11];
  const float* w3       = (const float*)d_in[12];
  const float* b3       = (const float*)d_in[13];
  const float* ln2_g    = (const float*)d_in[14];
  const float* ln2_b    = (const float*)d_in[15];
  const float* qkv2_w   = (const float*)d_in[16];
  const float* out2_w   = (const float*)d_in[17];
  const float* out2_b   = (const float*)d_in[18];
  const float* res2_w   = (const float*)d_in[19];
  const float* lnf_g    = (const float*)d_in[20];
  const float* lnf_b    = (const float*)d_in[21];

  cudaFuncSetAttribute((const void*)a1w2f_k, cudaFuncAttributeMaxDynamicSharedMemorySize, DSM_A1W2F);

  float* base = nullptr;
  cudaGetSymbolAddress((void**)&base, g_scratch);

  static cudaStream_t sB = nullptr, sC = nullptr;
  static cudaEvent_t eF1, eJ1, eC1, eF2, eJ2, eC2;
  if (!sB){
    cudaStreamCreateWithFlags(&sB, cudaStreamNonBlocking);
    cudaStreamCreateWithFlags(&sC, cudaStreamNonBlocking);
    cudaEventCreateWithFlags(&eF1, cudaEventDisableTiming);
    cudaEventCreateWithFlags(&eJ1, cudaEventDisableTiming);
    cudaEventCreateWithFlags(&eC1, cudaEventDisableTiming);
    cudaEventCreateWithFlags(&eF2, cudaEventDisableTiming);
    cudaEventCreateWithFlags(&eJ2, cudaEventDisableTiming);
    cudaEventCreateWithFlags(&eC2, cudaEventDisableTiming);
  }

  float* hA = base + OFF_HA;
  float* hB = base + OFF_HB;

  roundh_copy_k<<<(unsigned)(((long)CDIM*KQKV+255)/256),256>>>(qkv1_w, (__half*)(base + OFF_W1R), (long)CDIM*KQKV);
  roundh_copy_k<<<(unsigned)(((long)CDIM*CDIM+255)/256),256>>>(out1_w, (__half*)(base + OFF_O1R), (long)CDIM*CDIM);
  roundh_copy_k<<<(unsigned)(((long)CDIM*KQKV+255)/256),256>>>(qkv2_w, (__half*)(base + OFF_W2R), (long)CDIM*KQKV);
  roundh_copy_k<<<(unsigned)(((long)CDIM*CDIM+255)/256),256>>>(out2_w, (__half*)(base + OFF_O2R), (long)CDIM*CDIM);

  init_h_k<<<(unsigned)((SZ_H + 255)/256), 256>>>(features, cls, hA);
  zero_k<<<(unsigned)(((long)PADN*CDIM/2 + 255)/256), 256>>>(base + OFF_LNX, (long)PADN*CDIM/2);

  run_attn_block(base, hA, ln1_g, ln1_b, (__half*)(base + OFF_W1R), (__half*)(base + OFF_O1R),
                 out1_b, res1_w, sB, sC, eF1, eJ1, eC1);

  build_wc_k<<<CDIM, 49>>>(w7, w5, w3, base + OFF_WC);
  cls_copy_k<<<1,256>>>(hA, hB);
  ppeg_k<<<dim3(2500, 4), 128>>>(hA, hB, base + OFF_WC, b7, b5, b3);

  run_attn_block(base, hB, ln2_g, ln2_b, (__half*)(base + OFF_W2R), (__half*)(base + OFF_O2R),
                 out2_b, res2_w, sB, sC, eF2, eJ2, eC2);

  ln_k<<<NTOK, 128>>>(hB, (float*)d_out, lnf_g, lnf_b);
}